// round 11
// baseline (speedup 1.0000x reference)
#include <cuda_runtime.h>
#include <cuda_fp16.h>
#include <math_constants.h>
#include <cstdint>

#define D_IN   2048
#define D_OUT  2048
#define HD     128
#define NG     4
#define HPG    4
#define SEQ    2048
#define GK     2048      /* K dim of every GEMM */

// ---------------- scratch (no cudaMalloc allowed) ----------------
__device__ __half g_Xh [4096 * 2048];   // x, fp16
__device__ __half g_WqT[2048 * 2048];   // Wq^T [n][k] fp16
__device__ __half g_WkT[512  * 2048];
__device__ __half g_WvT[512  * 2048];
__device__ __half g_WoT[2048 * 2048];
__device__ __half g_Qh [4096 * 2048];   // q proj, scaled, fp16 [seq][dim]
__device__ __half g_Kh [4096 * 512];    // k proj fp16 [seq][gdim]
__device__ __half g_Vt [8 * 128 * 2048];// v proj TRANSPOSED [b*g][dim][seq]
__device__ __half g_Ch [4096 * 2048];   // ctx fp16

// ---------------- helpers ----------------
__device__ __forceinline__ void mma_f16(float* d, const uint32_t* a, const uint32_t* b) {
    asm volatile(
        "mma.sync.aligned.m16n8k16.row.col.f32.f16.f16.f32 "
        "{%0,%1,%2,%3}, {%4,%5,%6,%7}, {%8,%9}, {%0,%1,%2,%3};"
        : "+f"(d[0]), "+f"(d[1]), "+f"(d[2]), "+f"(d[3])
        : "r"(a[0]), "r"(a[1]), "r"(a[2]), "r"(a[3]), "r"(b[0]), "r"(b[1]));
}
__device__ __forceinline__ uint32_t smem_u32(const void* p) {
    uint32_t a;
    asm("{ .reg .u64 t; cvta.to.shared.u64 t, %1; cvt.u32.u64 %0, t; }" : "=r"(a) : "l"(p));
    return a;
}
__device__ __forceinline__ uint32_t packh2(float x, float y) {
    __half2 h = __floats2half2_rn(x, y);
    return *(uint32_t*)&h;
}
#define LDSM_X4(r0, r1, r2, r3, addr) \
    asm volatile("ldmatrix.sync.aligned.m8n8.x4.shared.b16 {%0,%1,%2,%3}, [%4];" \
        : "=r"(r0), "=r"(r1), "=r"(r2), "=r"(r3) : "r"(addr))
#define CP_ASYNC16(dst, src) \
    asm volatile("cp.async.cg.shared.global [%0], [%1], 16;" :: "r"(dst), "l"(src) : "memory")
#define CP_COMMIT() asm volatile("cp.async.commit_group;" ::: "memory")
#define CP_WAIT0()  asm volatile("cp.async.wait_group 0;" ::: "memory")
#define CP_WAIT1()  asm volatile("cp.async.wait_group 1;" ::: "memory")

#define SCALE 0.08838834764831845f   /* 1/sqrt(128) */

// ---------------- prepass ----------------
__global__ void cvt_x(const float* __restrict__ in, __half* __restrict__ out) {
    size_t i = ((size_t)blockIdx.x * blockDim.x + threadIdx.x) * 4;
    float4 v = *(const float4*)(in + i);
    uint2 o;
    o.x = packh2(v.x, v.y);
    o.y = packh2(v.z, v.w);
    *(uint2*)(out + i) = o;
}

// paired transpose: z=0 -> (W0,Wt0), z=1 -> (W1,Wt1).  W [K][N] -> Wt [N][K] fp16
__global__ void transpose2_h(const float* __restrict__ W0, __half* __restrict__ Wt0,
                             const float* __restrict__ W1, __half* __restrict__ Wt1,
                             int K, int N) {
    __shared__ float t[32][33];
    const float* W = blockIdx.z ? W1 : W0;
    __half* Wt = blockIdx.z ? Wt1 : Wt0;
    int x = blockIdx.x * 32 + threadIdx.x;   // n
    int y = blockIdx.y * 32 + threadIdx.y;   // k
#pragma unroll
    for (int i = 0; i < 32; i += 8)
        t[threadIdx.y + i][threadIdx.x] = W[(size_t)(y + i) * N + x];
    __syncthreads();
    int x2 = blockIdx.y * 32 + threadIdx.x;  // k
    int y2 = blockIdx.x * 32 + threadIdx.y;  // n
#pragma unroll
    for (int i = 0; i < 32; i += 8)
        Wt[(size_t)(y2 + i) * K + x2] = __float2half_rn(t[threadIdx.x][threadIdx.y + i]);
}

// -- fp16 mma GEMM: CTA 128x128, 8 warps @ 32x64, BK=64, 3-stage, 2 CTA/SM --
#define GLDB 144
#define GAS_B (128 * GLDB)
#define GSTG_B (2 * GAS_B)
#define GEMM_SMEM (3 * GSTG_B)            /* 110592 B */

template <bool PROJ>
__global__ __launch_bounds__(256, 2) void gemm_h(
    const __half* __restrict__ A,
    const __half* __restrict__ B0, const __half* __restrict__ B1,
    const __half* __restrict__ B2,
    __half* __restrict__ Qo, __half* __restrict__ Ko, __half* __restrict__ Vo,
    float* __restrict__ Co, const float* __restrict__ bias)
{
    extern __shared__ char smc[];
    const int tid = threadIdx.x;
    const int wid = tid >> 5, l = tid & 31;
    const int lq = l >> 2, lr = l & 3;
    const int m0 = blockIdx.y * 128;
    const int n0 = blockIdx.x * 128;
    const int wm = (wid & 3) * 32, wn = (wid >> 2) * 64;
    const uint32_t smb = smem_u32(smc);

    const __half* Bp;
    if (PROJ) {
        if (n0 < 2048)      Bp = B0 + (size_t)n0 * GK;
        else if (n0 < 2560) Bp = B1 + (size_t)(n0 - 2048) * GK;
        else                Bp = B2 + (size_t)(n0 - 2560) * GK;
    } else Bp = B0 + (size_t)n0 * GK;

    float acc[2][8][4];
#pragma unroll
    for (int i = 0; i < 2; i++)
#pragma unroll
        for (int j = 0; j < 8; j++)
#pragma unroll
            for (int r = 0; r < 4; r++) acc[i][j][r] = 0.f;

    const uint32_t a_lane = (uint32_t)((wm + (l & 15)) * GLDB + (l >> 4) * 16);
    const uint32_t b_lane = (uint32_t)((wn + (l & 7) + ((l >> 4) << 3)) * GLDB
                                       + ((l >> 3) & 1) * 16);

#define G_LOAD(s, kc) do {                                                        \
        uint32_t _ab = smb + (s) * GSTG_B;                                        \
        uint32_t _bb = _ab + GAS_B;                                               \
        _Pragma("unroll")                                                         \
        for (int _i = 0; _i < 4; _i++) {                                          \
            int _e = tid + _i * 256, _r = _e >> 3, _ch = _e & 7;                  \
            CP_ASYNC16(_ab + _r * GLDB + _ch * 16,                                \
                (const void*)(A + (size_t)(m0 + _r) * GK + (kc) * 64 + _ch * 8)); \
            CP_ASYNC16(_bb + _r * GLDB + _ch * 16,                                \
                (const void*)(Bp + (size_t)_r * GK + (kc) * 64 + _ch * 8));       \
        }                                                                         \
    } while (0)

    G_LOAD(0, 0); CP_COMMIT();
    G_LOAD(1, 1); CP_COMMIT();

    const int kiters = GK / 64;
    for (int it = 0; it < kiters; it++) {
        CP_WAIT1();
        __syncthreads();
        if (it + 2 < kiters) { G_LOAD((it + 2) % 3, it + 2); CP_COMMIT(); }

        const uint32_t abase = smb + (it % 3) * GSTG_B + a_lane;
        const uint32_t bbase = smb + (it % 3) * GSTG_B + GAS_B + b_lane;

#pragma unroll
        for (int ks = 0; ks < 4; ks++) {
            uint32_t af[2][4], bf[8][2];
#pragma unroll
            for (int mf = 0; mf < 2; mf++)
                LDSM_X4(af[mf][0], af[mf][1], af[mf][2], af[mf][3],
                        abase + mf * (16 * GLDB) + ks * 32);
#pragma unroll
            for (int p = 0; p < 4; p++)
                LDSM_X4(bf[2 * p][0], bf[2 * p][1], bf[2 * p + 1][0], bf[2 * p + 1][1],
                        bbase + p * (16 * GLDB) + ks * 32);
#pragma unroll
            for (int mf = 0; mf < 2; mf++)
#pragma unroll
                for (int nf = 0; nf < 8; nf++)
                    mma_f16(acc[mf][nf], af[mf], bf[nf]);
        }
        __syncthreads();
    }

    // epilogue
#pragma unroll
    for (int mf = 0; mf < 2; mf++) {
        const int row = m0 + wm + mf * 16 + lq;
#pragma unroll
        for (int nf = 0; nf < 8; nf++) {
            const int col = wn + nf * 8 + 2 * lr;
            const float c0 = acc[mf][nf][0], c1 = acc[mf][nf][1];
            const float c2 = acc[mf][nf][2], c3 = acc[mf][nf][3];
            if (!PROJ) {
                float2 b = *(const float2*)(bias + n0 + col);
                *(float2*)(Co + (size_t)row * 2048 + n0 + col) =
                    make_float2(c0 + b.x, c1 + b.y);
                *(float2*)(Co + (size_t)(row + 8) * 2048 + n0 + col) =
                    make_float2(c2 + b.x, c3 + b.y);
            } else if (n0 < 2048) {
                *(uint32_t*)(Qo + (size_t)row * 2048 + n0 + col) =
                    packh2(c0 * SCALE, c1 * SCALE);
                *(uint32_t*)(Qo + (size_t)(row + 8) * 2048 + n0 + col) =
                    packh2(c2 * SCALE, c3 * SCALE);
            } else if (n0 < 2560) {
                const int kc = n0 - 2048 + col;
                *(uint32_t*)(Ko + (size_t)row * 512 + kc) = packh2(c0, c1);
                *(uint32_t*)(Ko + (size_t)(row + 8) * 512 + kc) = packh2(c2, c3);
            } else {
                const int vd = n0 - 2560 + col;
                const int gi = vd >> 7, d = vd & 127;
                const int bi = row >> 11, s = row & 2047;
                __half* vb = Vo + ((size_t)(bi * NG + gi) * 128 + d) * 2048;
                vb[s]            = __float2half_rn(c0);
                vb[2048 + s]     = __float2half_rn(c1);
                vb[s + 8]        = __float2half_rn(c2);
                vb[2048 + s + 8] = __float2half_rn(c3);
            }
        }
    }
#undef G_LOAD
}

// ---- fp16 mma flash-attention: CTA 64 q-rows, 4x2 warps (16q x 32keys),
// ---- 64-key double-buffered tiles, 2 CTAs/SM.
#define QS_B (64 * 272)                   /* 17408 */
#define KS_B (64 * 272)                   /* 17408 */
#define VLDB 144
#define VS_B (128 * VLDB)                 /* 18432 */
#define ATTN_SMEM (QS_B + 2 * KS_B + 2 * VS_B)   /* 89088 B */

__global__ __launch_bounds__(256, 2) void attn_h(
    const __half* __restrict__ Q, const __half* __restrict__ K,
    const __half* __restrict__ VT, __half* __restrict__ C)
{
    extern __shared__ char smc[];
    const int tid = threadIdx.x;
    const int wid = tid >> 5, l = tid & 31;
    const int lq = l >> 2, lr = l & 3;
    const int wr = wid >> 1, wc = wid & 1;
    const int wq = wr * 16;                  // warp's 16-q strip
    const int koff = wc * 32;                // warp's 32-key half

    const int qc = gridDim.x - 1 - blockIdx.x;   // long CTAs first
    const int hh = blockIdx.y;
    const int bi = hh >> 4;
    const int gi = (hh >> 2) & 3;
    const int hi = hh & 3;
    const int qcol = (gi * HPG + hi) * HD;
    const int kcol = gi * HD;
    const size_t rowbase = (size_t)bi * SEQ;
    const int qbase = qc * 64;
    const uint32_t smb = smem_u32(smc);
    const __half* vtb = VT + (size_t)(bi * NG + gi) * 128 * 2048;

    const uint32_t qa_lane = (uint32_t)((wq + (l & 15)) * 272 + (l >> 4) * 16);
    const uint32_t kb_lane = (uint32_t)((koff + (l & 7) + ((l >> 4) << 3)) * 272
                                        + ((l >> 3) & 1) * 16);
    const uint32_t vb_lane = (uint32_t)(((l & 7) + ((l >> 4) << 3)) * VLDB
                                        + ((l >> 3) & 1) * 16 + koff * 2);

    // ---- Q tile [64 q][128 d]: 1024 chunks, 4/thread ----
#pragma unroll
    for (int u = 0; u < 4; u++) {
        int e = tid + u * 256, r = e >> 4, ch = e & 15;
        CP_ASYNC16(smb + r * 272 + ch * 16,
                   (const void*)(Q + (rowbase + qbase + r) * 2048 + qcol + ch * 8));
    }

    float o[16][4];
#pragma unroll
    for (int i = 0; i < 16; i++)
#pragma unroll
        for (int r = 0; r < 4; r++) o[i][r] = 0.f;
    float m0 = -CUDART_INF_F, m1 = -CUDART_INF_F, l0 = 0.f, l1 = 0.f;

    const int jmax = qc;

    // K tile: 64 keys x 128 d = 1024 chunks; V tile: 128 d x 64 keys = 1024 chunks
#define KV_LOAD(ss, jj) do {                                                     \
        uint32_t _kb = smb + QS_B + (ss) * KS_B;                                  \
        uint32_t _vb = smb + QS_B + 2 * KS_B + (ss) * VS_B;                       \
        _Pragma("unroll")                                                         \
        for (int _u = 0; _u < 4; _u++) {                                          \
            int _e = tid + _u * 256;                                              \
            int _kr = _e >> 4, _kc = _e & 15;                                     \
            CP_ASYNC16(_kb + _kr * 272 + _kc * 16,                                \
                (const void*)(K + (rowbase + (jj) * 64 + _kr) * 512 + kcol + _kc * 8)); \
            int _vr = _e >> 3, _vc = _e & 7;                                      \
            CP_ASYNC16(_vb + _vr * VLDB + _vc * 16,                               \
                (const void*)(vtb + (size_t)_vr * 2048 + (jj) * 64 + _vc * 8));   \
        }                                                                         \
    } while (0)

    KV_LOAD(0, 0); CP_COMMIT();

    for (int j = 0; j <= jmax; j++) {
        CP_WAIT0();
        __syncthreads();
        if (j < jmax) { KV_LOAD((j + 1) & 1, j + 1); CP_COMMIT(); }

        const int st = j & 1;
        const uint32_t ksb = smb + QS_B + st * KS_B;
        const uint32_t vsb = smb + QS_B + 2 * KS_B + st * VS_B;
        const int kb = j * 64 + koff;
        if (kb > qbase + wq + 15) continue;   // warp's 32-key half fully masked

        // ---- S = Q @ K^T : 16 q x 32 keys ----
        float s_[4][4];
#pragma unroll
        for (int nf = 0; nf < 4; nf++)
#pragma unroll
            for (int r = 0; r < 4; r++) s_[nf][r] = 0.f;

#pragma unroll
        for (int kf = 0; kf < 8; kf++) {
            uint32_t qa[4], kbf[4][2];
            LDSM_X4(qa[0], qa[1], qa[2], qa[3], smb + qa_lane + kf * 32);
#pragma unroll
            for (int p = 0; p < 2; p++)
                LDSM_X4(kbf[2 * p][0], kbf[2 * p][1], kbf[2 * p + 1][0], kbf[2 * p + 1][1],
                        ksb + kb_lane + p * (16 * 272) + kf * 32);
#pragma unroll
            for (int nf = 0; nf < 4; nf++)
                mma_f16(s_[nf], qa, kbf[nf]);
        }

        // ---- per-warp softmax over its 32-key half ----
        const bool needmask = (kb + 31 > qbase + wq);
        const int gr0 = qbase + wq + lq;
        const int gr1 = gr0 + 8;
        float mx0 = -CUDART_INF_F, mx1 = -CUDART_INF_F;
#pragma unroll
        for (int nf = 0; nf < 4; nf++) {
            if (needmask) {
                const int c0 = kb + nf * 8 + 2 * lr;
                if (c0 > gr0)     s_[nf][0] = -CUDART_INF_F;
                if (c0 + 1 > gr0) s_[nf][1] = -CUDART_INF_F;
                if (c0 > gr1)     s_[nf][2] = -CUDART_INF_F;
                if (c0 + 1 > gr1) s_[nf][3] = -CUDART_INF_F;
            }
            mx0 = fmaxf(mx0, fmaxf(s_[nf][0], s_[nf][1]));
            mx1 = fmaxf(mx1, fmaxf(s_[nf][2], s_[nf][3]));
        }
#pragma unroll
        for (int msk = 1; msk < 4; msk <<= 1) {
            mx0 = fmaxf(mx0, __shfl_xor_sync(0xffffffffu, mx0, msk));
            mx1 = fmaxf(mx1, __shfl_xor_sync(0xffffffffu, mx1, msk));
        }
        const float nm0 = fmaxf(m0, mx0);
        const float nm1 = fmaxf(m1, mx1);
        const float al0 = __expf(m0 - nm0);
        const float al1 = __expf(m1 - nm1);
        m0 = nm0; m1 = nm1;

        float sm0 = 0.f, sm1 = 0.f;
#pragma unroll
        for (int nf = 0; nf < 4; nf++) {
            float p0 = __expf(s_[nf][0] - nm0);
            float p1 = __expf(s_[nf][1] - nm0);
            float p2 = __expf(s_[nf][2] - nm1);
            float p3 = __expf(s_[nf][3] - nm1);
            sm0 += p0 + p1; sm1 += p2 + p3;
            s_[nf][0] = p0; s_[nf][1] = p1;
            s_[nf][2] = p2; s_[nf][3] = p3;
        }
#pragma unroll
        for (int msk = 1; msk < 4; msk <<= 1) {
            sm0 += __shfl_xor_sync(0xffffffffu, sm0, msk);
            sm1 += __shfl_xor_sync(0xffffffffu, sm1, msk);
        }
        l0 = l0 * al0 + sm0;
        l1 = l1 * al1 + sm1;
#pragma unroll
        for (int nf = 0; nf < 16; nf++) {
            o[nf][0] *= al0; o[nf][1] *= al0;
            o[nf][2] *= al1; o[nf][3] *= al1;
        }
        // pack P c-frags into fp16 a-frags (32 keys = 2 k-frags)
        uint32_t P2[2][4];
#pragma unroll
        for (int kf = 0; kf < 2; kf++) {
            P2[kf][0] = packh2(s_[2 * kf][0],     s_[2 * kf][1]);
            P2[kf][1] = packh2(s_[2 * kf][2],     s_[2 * kf][3]);
            P2[kf][2] = packh2(s_[2 * kf + 1][0], s_[2 * kf + 1][1]);
            P2[kf][3] = packh2(s_[2 * kf + 1][2], s_[2 * kf + 1][3]);
        }

        // ---- O += P @ V ----
#pragma unroll
        for (int kf = 0; kf < 2; kf++) {
            uint32_t vbf[16][2];
#pragma unroll
            for (int p = 0; p < 8; p++)
                LDSM_X4(vbf[2 * p][0], vbf[2 * p][1], vbf[2 * p + 1][0], vbf[2 * p + 1][1],
                        vsb + vb_lane + p * (16 * VLDB) + kf * 32);
#pragma unroll
            for (int nf = 0; nf < 16; nf++)
                mma_f16(o[nf], P2[kf], vbf[nf]);
        }
    }

    // ---- merge key-halves (wc=1 publishes, wc=0 combines + stores) ----
    float* Ox = (float*)smc;                 // [4 strips][16][132] fp32
    float* St = Ox + 4 * 16 * 132;           // [64][2]
    __syncthreads();
    if (wc == 1) {
        float* ob = Ox + wr * 16 * 132;
#pragma unroll
        for (int nf = 0; nf < 16; nf++) {
            const int col = nf * 8 + 2 * lr;
            *(float2*)&ob[lq * 132 + col]       = make_float2(o[nf][0], o[nf][1]);
            *(float2*)&ob[(lq + 8) * 132 + col] = make_float2(o[nf][2], o[nf][3]);
        }
        if (lr == 0) {
            float* st = St + (wr * 16 + lq) * 2;
            st[0] = m0; st[1] = l0;
            st[16] = m1; st[17] = l1;    // row lq+8
        }
    }
    __syncthreads();
    if (wc == 0) {
        const float* ob = Ox + wr * 16 * 132;
        const float* st = St + (wr * 16 + lq) * 2;
        const float mo0 = st[0],  lo0 = st[1];
        const float mo1 = st[16], lo1 = st[17];
        const float M0 = fmaxf(m0, mo0);
        const float M1 = fmaxf(m1, mo1);
        const float as0 = __expf(m0 - M0), ao0 = __expf(mo0 - M0);
        const float as1 = __expf(m1 - M1), ao1 = __expf(mo1 - M1);
        const float inv0 = 1.f / (l0 * as0 + lo0 * ao0);
        const float inv1 = 1.f / (l1 * as1 + lo1 * ao1);
        const float fs0 = as0 * inv0, fo0 = ao0 * inv0;
        const float fs1 = as1 * inv1, fo1 = ao1 * inv1;
        const size_t r0 = rowbase + qbase + wq + lq;
        const size_t r1 = r0 + 8;
#pragma unroll
        for (int nf = 0; nf < 16; nf++) {
            const int col = nf * 8 + 2 * lr;
            float2 q0 = *(const float2*)&ob[lq * 132 + col];
            float2 q1 = *(const float2*)&ob[(lq + 8) * 132 + col];
            *(uint32_t*)(C + r0 * 2048 + qcol + col) =
                packh2(o[nf][0] * fs0 + q0.x * fo0,
                       o[nf][1] * fs0 + q0.y * fo0);
            *(uint32_t*)(C + r1 * 2048 + qcol + col) =
                packh2(o[nf][2] * fs1 + q1.x * fo1,
                       o[nf][3] * fs1 + q1.y * fo1);
        }
    }
#undef KV_LOAD
}

// ---------------------------------------------------------------------------
extern "C" void kernel_launch(void* const* d_in, const int* in_sizes, int n_in,
                              void* d_out, int out_size)
{
    const float* x  = (const float*)d_in[0];
    const float* Wq = (const float*)d_in[1];
    const float* Wk = (const float*)d_in[2];
    const float* Wv = (const float*)d_in[3];
    const float* Wo = (const float*)d_in[4];
    const float* bo = (const float*)d_in[5];

    const int M = in_sizes[0] / D_IN;   // 4096
    const int B = M / SEQ;              // 2

    __half *Xh, *WqT, *WkT, *WvT, *WoT, *Qh, *Kh, *Vt, *Ch;
    cudaGetSymbolAddress((void**)&Xh,  g_Xh);
    cudaGetSymbolAddress((void**)&WqT, g_WqT);
    cudaGetSymbolAddress((void**)&WkT, g_WkT);
    cudaGetSymbolAddress((void**)&WvT, g_WvT);
    cudaGetSymbolAddress((void**)&WoT, g_WoT);
    cudaGetSymbolAddress((void**)&Qh,  g_Qh);
    cudaGetSymbolAddress((void**)&Kh,  g_Kh);
    cudaGetSymbolAddress((void**)&Vt,  g_Vt);
    cudaGetSymbolAddress((void**)&Ch,  g_Ch);

    cudaFuncSetAttribute(gemm_h<true>,
                         cudaFuncAttributeMaxDynamicSharedMemorySize, GEMM_SMEM);
    cudaFuncSetAttribute(gemm_h<false>,
                         cudaFuncAttributeMaxDynamicSharedMemorySize, GEMM_SMEM);
    cudaFuncSetAttribute(attn_h,
                         cudaFuncAttributeMaxDynamicSharedMemorySize, ATTN_SMEM);

    // prepass: fp16 conversions + paired weight transposes
    cvt_x<<<(M * D_IN) / 1024, 256>>>(x, Xh);
    transpose2_h<<<dim3(64, 64, 2), dim3(32, 8)>>>(Wq, WqT, Wo, WoT, 2048, 2048);
    transpose2_h<<<dim3(16, 64, 2), dim3(32, 8)>>>(Wk, WkT, Wv, WvT, 2048, 512);

    // fused QKV projection: N = 2048 (Q) + 512 (K) + 512 (V^T) = 3072
    gemm_h<true><<<dim3(24, M / 128), 256, GEMM_SMEM>>>(
        Xh, WqT, WkT, WvT, Qh, Kh, Vt, nullptr, nullptr);

    attn_h<<<dim3(SEQ / 64, B * 16), 256, ATTN_SMEM>>>(Qh, Kh, Vt, Ch);

    // output projection + bias (fp32 out)
    gemm_h<false><<<dim3(16, M / 128), 256, GEMM_SMEM>>>(
        Ch, WoT, nullptr, nullptr, nullptr, nullptr, nullptr, (float*)d_out, bo);
}

// round 12
// speedup vs baseline: 1.5310x; 1.5310x over previous
#include <cuda_runtime.h>
#include <cuda_fp16.h>
#include <math_constants.h>
#include <cstdint>

#define D_IN   2048
#define D_OUT  2048
#define HD     128
#define NG     4
#define HPG    4
#define SEQ    2048
#define GK     2048      /* K dim of every GEMM */

// ---------------- scratch (no cudaMalloc allowed) ----------------
__device__ __half g_Xh [4096 * 2048];   // x, fp16
__device__ __half g_WqT[2048 * 2048];   // Wq^T [n][k] fp16
__device__ __half g_WkT[512  * 2048];
__device__ __half g_WvT[512  * 2048];
__device__ __half g_WoT[2048 * 2048];
__device__ __half g_Qh [4096 * 2048];   // q proj, scaled, fp16 [seq][dim]
__device__ __half g_Kh [4096 * 512];    // k proj fp16 [seq][gdim]
__device__ __half g_Vt [8 * 128 * 2048];// v proj TRANSPOSED [b*g][dim][seq]
__device__ __half g_Ch [4096 * 2048];   // ctx fp16

// ---------------- helpers ----------------
__device__ __forceinline__ void mma_f16(float* d, const uint32_t* a, const uint32_t* b) {
    asm volatile(
        "mma.sync.aligned.m16n8k16.row.col.f32.f16.f16.f32 "
        "{%0,%1,%2,%3}, {%4,%5,%6,%7}, {%8,%9}, {%0,%1,%2,%3};"
        : "+f"(d[0]), "+f"(d[1]), "+f"(d[2]), "+f"(d[3])
        : "r"(a[0]), "r"(a[1]), "r"(a[2]), "r"(a[3]), "r"(b[0]), "r"(b[1]));
}
__device__ __forceinline__ uint32_t smem_u32(const void* p) {
    uint32_t a;
    asm("{ .reg .u64 t; cvta.to.shared.u64 t, %1; cvt.u32.u64 %0, t; }" : "=r"(a) : "l"(p));
    return a;
}
__device__ __forceinline__ uint32_t packh2(float x, float y) {
    __half2 h = __floats2half2_rn(x, y);
    return *(uint32_t*)&h;
}
#define LDSM_X4(r0, r1, r2, r3, addr) \
    asm volatile("ldmatrix.sync.aligned.m8n8.x4.shared.b16 {%0,%1,%2,%3}, [%4];" \
        : "=r"(r0), "=r"(r1), "=r"(r2), "=r"(r3) : "r"(addr))
#define CP_ASYNC16(dst, src) \
    asm volatile("cp.async.cg.shared.global [%0], [%1], 16;" :: "r"(dst), "l"(src) : "memory")
#define CP_COMMIT() asm volatile("cp.async.commit_group;" ::: "memory")
#define CP_WAIT0()  asm volatile("cp.async.wait_group 0;" ::: "memory")
#define CP_WAIT1()  asm volatile("cp.async.wait_group 1;" ::: "memory")

#define SCALE 0.08838834764831845f   /* 1/sqrt(128) */

// ---------------- prepass ----------------
__global__ void cvt_x(const float* __restrict__ in, __half* __restrict__ out) {
    size_t i = ((size_t)blockIdx.x * blockDim.x + threadIdx.x) * 4;
    float4 v = *(const float4*)(in + i);
    uint2 o;
    o.x = packh2(v.x, v.y);
    o.y = packh2(v.z, v.w);
    *(uint2*)(out + i) = o;
}

// paired transpose: z=0 -> (W0,Wt0), z=1 -> (W1,Wt1).  W [K][N] -> Wt [N][K] fp16
__global__ void transpose2_h(const float* __restrict__ W0, __half* __restrict__ Wt0,
                             const float* __restrict__ W1, __half* __restrict__ Wt1,
                             int K, int N) {
    __shared__ float t[32][33];
    const float* W = blockIdx.z ? W1 : W0;
    __half* Wt = blockIdx.z ? Wt1 : Wt0;
    int x = blockIdx.x * 32 + threadIdx.x;   // n
    int y = blockIdx.y * 32 + threadIdx.y;   // k
#pragma unroll
    for (int i = 0; i < 32; i += 8)
        t[threadIdx.y + i][threadIdx.x] = W[(size_t)(y + i) * N + x];
    __syncthreads();
    int x2 = blockIdx.y * 32 + threadIdx.x;  // k
    int y2 = blockIdx.x * 32 + threadIdx.y;  // n
#pragma unroll
    for (int i = 0; i < 32; i += 8)
        Wt[(size_t)(y2 + i) * K + x2] = __float2half_rn(t[threadIdx.x][threadIdx.y + i]);
}

// -- fp16 mma GEMM: CTA 128x128, 8 warps @ 32x64, BK=64, 3-stage, 2 CTA/SM --
#define GLDB 144                          /* smem row stride bytes (64h + pad) */
#define GAS_B (128 * GLDB)                /* 18432 B */
#define GSTG_B (2 * GAS_B)                /* 36864 B */
#define GEMM_SMEM (3 * GSTG_B)            /* 110592 B */

template <bool PROJ>
__global__ __launch_bounds__(256, 2) void gemm_h(
    const __half* __restrict__ A,
    const __half* __restrict__ B0, const __half* __restrict__ B1,
    const __half* __restrict__ B2,
    __half* __restrict__ Qo, __half* __restrict__ Ko, __half* __restrict__ Vo,
    float* __restrict__ Co, const float* __restrict__ bias)
{
    extern __shared__ char smc[];
    const int tid = threadIdx.x;
    const int wid = tid >> 5, l = tid & 31;
    const int lq = l >> 2, lr = l & 3;
    const int m0 = blockIdx.y * 128;
    const int n0 = blockIdx.x * 128;
    const int wm = (wid & 3) * 32, wn = (wid >> 2) * 64;
    const uint32_t smb = smem_u32(smc);

    const __half* Bp;
    if (PROJ) {
        if (n0 < 2048)      Bp = B0 + (size_t)n0 * GK;
        else if (n0 < 2560) Bp = B1 + (size_t)(n0 - 2048) * GK;
        else                Bp = B2 + (size_t)(n0 - 2560) * GK;
    } else Bp = B0 + (size_t)n0 * GK;

    float acc[2][8][4];
#pragma unroll
    for (int i = 0; i < 2; i++)
#pragma unroll
        for (int j = 0; j < 8; j++)
#pragma unroll
            for (int r = 0; r < 4; r++) acc[i][j][r] = 0.f;

    const uint32_t a_lane = (uint32_t)((wm + (l & 15)) * GLDB + (l >> 4) * 16);
    const uint32_t b_lane = (uint32_t)((wn + (l & 7) + ((l >> 4) << 3)) * GLDB
                                       + ((l >> 3) & 1) * 16);

#define G_LOAD(s, kc) do {                                                        \
        uint32_t _ab = smb + (s) * GSTG_B;                                        \
        uint32_t _bb = _ab + GAS_B;                                               \
        _Pragma("unroll")                                                         \
        for (int _i = 0; _i < 4; _i++) {                                          \
            int _e = tid + _i * 256, _r = _e >> 3, _ch = _e & 7;                  \
            CP_ASYNC16(_ab + _r * GLDB + _ch * 16,                                \
                (const void*)(A + (size_t)(m0 + _r) * GK + (kc) * 64 + _ch * 8)); \
            CP_ASYNC16(_bb + _r * GLDB + _ch * 16,                                \
                (const void*)(Bp + (size_t)_r * GK + (kc) * 64 + _ch * 8));       \
        }                                                                         \
    } while (0)

    G_LOAD(0, 0); CP_COMMIT();
    G_LOAD(1, 1); CP_COMMIT();

    const int kiters = GK / 64;   // 32
    for (int it = 0; it < kiters; it++) {
        CP_WAIT1();
        __syncthreads();
        if (it + 2 < kiters) { G_LOAD((it + 2) % 3, it + 2); CP_COMMIT(); }

        const uint32_t abase = smb + (it % 3) * GSTG_B + a_lane;
        const uint32_t bbase = smb + (it % 3) * GSTG_B + GAS_B + b_lane;

#pragma unroll
        for (int ks = 0; ks < 4; ks++) {
            uint32_t af[2][4], bf[8][2];
#pragma unroll
            for (int mf = 0; mf < 2; mf++)
                LDSM_X4(af[mf][0], af[mf][1], af[mf][2], af[mf][3],
                        abase + mf * (16 * GLDB) + ks * 32);
#pragma unroll
            for (int p = 0; p < 4; p++)
                LDSM_X4(bf[2 * p][0], bf[2 * p][1], bf[2 * p + 1][0], bf[2 * p + 1][1],
                        bbase + p * (16 * GLDB) + ks * 32);
#pragma unroll
            for (int mf = 0; mf < 2; mf++)
#pragma unroll
                for (int nf = 0; nf < 8; nf++)
                    mma_f16(acc[mf][nf], af[mf], bf[nf]);
        }
        __syncthreads();
    }

    // epilogue
#pragma unroll
    for (int mf = 0; mf < 2; mf++) {
        const int row = m0 + wm + mf * 16 + lq;
#pragma unroll
        for (int nf = 0; nf < 8; nf++) {
            const int col = wn + nf * 8 + 2 * lr;
            const float c0 = acc[mf][nf][0], c1 = acc[mf][nf][1];
            const float c2 = acc[mf][nf][2], c3 = acc[mf][nf][3];
            if (!PROJ) {
                float2 b = *(const float2*)(bias + n0 + col);
                *(float2*)(Co + (size_t)row * 2048 + n0 + col) =
                    make_float2(c0 + b.x, c1 + b.y);
                *(float2*)(Co + (size_t)(row + 8) * 2048 + n0 + col) =
                    make_float2(c2 + b.x, c3 + b.y);
            } else if (n0 < 2048) {
                *(uint32_t*)(Qo + (size_t)row * 2048 + n0 + col) =
                    packh2(c0 * SCALE, c1 * SCALE);
                *(uint32_t*)(Qo + (size_t)(row + 8) * 2048 + n0 + col) =
                    packh2(c2 * SCALE, c3 * SCALE);
            } else if (n0 < 2560) {
                const int kc = n0 - 2048 + col;
                *(uint32_t*)(Ko + (size_t)row * 512 + kc) = packh2(c0, c1);
                *(uint32_t*)(Ko + (size_t)(row + 8) * 512 + kc) = packh2(c2, c3);
            } else {
                const int vd = n0 - 2560 + col;
                const int gi = vd >> 7, d = vd & 127;
                const int bi = row >> 11, s = row & 2047;
                __half* vb = Vo + ((size_t)(bi * NG + gi) * 128 + d) * 2048;
                vb[s]            = __float2half_rn(c0);
                vb[2048 + s]     = __float2half_rn(c1);
                vb[s + 8]        = __float2half_rn(c2);
                vb[2048 + s + 8] = __float2half_rn(c3);
            }
        }
    }
#undef G_LOAD
}

// -------- fp16 mma flash-attention: split-softmax 4x2 warps, 128-key tiles --
// (R10 configuration: CTA = 128 q-rows, 1 CTA/SM, 174 KB smem)
#define HLD 136
#define QS_B (128 * 272)
#define KS_B (128 * 272)
#define VS_B (128 * 272)
#define ATTN_SMEM (QS_B + 2 * KS_B + 2 * VS_B)   /* 174080 B */

__global__ __launch_bounds__(256, 1) void attn_h(
    const __half* __restrict__ Q, const __half* __restrict__ K,
    const __half* __restrict__ VT, __half* __restrict__ C)
{
    extern __shared__ char smc[];
    const int tid = threadIdx.x;
    const int wid = tid >> 5, l = tid & 31;
    const int lq = l >> 2, lr = l & 3;
    const int wr = wid >> 1, wc = wid & 1;
    const int wq = wr * 32;
    const int koff = wc * 64;

    const int qc = gridDim.x - 1 - blockIdx.x;   // long CTAs first
    const int hh = blockIdx.y;
    const int bi = hh >> 4;
    const int gi = (hh >> 2) & 3;
    const int hi = hh & 3;
    const int qcol = (gi * HPG + hi) * HD;
    const int kcol = gi * HD;
    const size_t rowbase = (size_t)bi * SEQ;
    const int qbase = qc * 128;
    const uint32_t smb = smem_u32(smc);
    const __half* vtb = VT + (size_t)(bi * NG + gi) * 128 * 2048;

    const uint32_t qa_lane = (uint32_t)((wq + (l & 15)) * 272 + (l >> 4) * 16);
    const uint32_t kb_lane = (uint32_t)((koff + (l & 7) + ((l >> 4) << 3)) * 272
                                        + ((l >> 3) & 1) * 16);
    const uint32_t vb_lane = (uint32_t)(((l & 7) + ((l >> 4) << 3)) * 272
                                        + ((l >> 3) & 1) * 16 + koff * 2);

    // ---- Q tile [128 q][128 d] fp16 ----
#pragma unroll
    for (int u = 0; u < 8; u++) {
        int e = tid + u * 256, r = e >> 4, ch = e & 15;
        CP_ASYNC16(smb + r * 272 + ch * 16,
                   (const void*)(Q + (rowbase + qbase + r) * 2048 + qcol + ch * 8));
    }

    float o[2][16][4];
#pragma unroll
    for (int mf = 0; mf < 2; mf++)
#pragma unroll
        for (int i = 0; i < 16; i++)
#pragma unroll
            for (int r = 0; r < 4; r++) o[mf][i][r] = 0.f;
    float mm[2][2], ll[2][2];
#pragma unroll
    for (int mf = 0; mf < 2; mf++) {
        mm[mf][0] = -CUDART_INF_F; mm[mf][1] = -CUDART_INF_F;
        ll[mf][0] = 0.f; ll[mf][1] = 0.f;
    }

    const int jmax = qc;

#define KV_LOAD(ss, jj) do {                                                     \
        uint32_t _kb = smb + QS_B + (ss) * KS_B;                                  \
        uint32_t _vb = smb + QS_B + 2 * KS_B + (ss) * VS_B;                       \
        _Pragma("unroll")                                                         \
        for (int _u = 0; _u < 8; _u++) {                                          \
            int _e = tid + _u * 256, _r = _e >> 4, _ch = _e & 15;                 \
            CP_ASYNC16(_kb + _r * 272 + _ch * 16,                                 \
                (const void*)(K + (rowbase + (jj) * 128 + _r) * 512 + kcol + _ch * 8)); \
            CP_ASYNC16(_vb + _r * 272 + _ch * 16,                                 \
                (const void*)(vtb + (size_t)_r * 2048 + (jj) * 128 + _ch * 8));   \
        }                                                                         \
    } while (0)

    KV_LOAD(0, 0); CP_COMMIT();

    for (int j = 0; j <= jmax; j++) {
        CP_WAIT0();
        __syncthreads();
        if (j < jmax) { KV_LOAD((j + 1) & 1, j + 1); CP_COMMIT(); }

        const int st = j & 1;
        const uint32_t ksb = smb + QS_B + st * KS_B;
        const uint32_t vsb = smb + QS_B + 2 * KS_B + st * VS_B;
        const int kb = j * 128 + koff;
        if (kb > qbase + wq + 31) continue;

        // ---- S = Q @ K^T : 32 q x 64 keys ----
        float s_[2][8][4];
#pragma unroll
        for (int mf = 0; mf < 2; mf++)
#pragma unroll
            for (int nf = 0; nf < 8; nf++)
#pragma unroll
                for (int r = 0; r < 4; r++) s_[mf][nf][r] = 0.f;

#pragma unroll
        for (int kf = 0; kf < 8; kf++) {
            uint32_t qa[2][4], kbf[8][2];
#pragma unroll
            for (int mf = 0; mf < 2; mf++)
                LDSM_X4(qa[mf][0], qa[mf][1], qa[mf][2], qa[mf][3],
                        smb + qa_lane + mf * (16 * 272) + kf * 32);
#pragma unroll
            for (int p = 0; p < 4; p++)
                LDSM_X4(kbf[2 * p][0], kbf[2 * p][1], kbf[2 * p + 1][0], kbf[2 * p + 1][1],
                        ksb + kb_lane + p * (16 * 272) + kf * 32);
#pragma unroll
            for (int nf = 0; nf < 8; nf++) {
                mma_f16(s_[0][nf], qa[0], kbf[nf]);
                mma_f16(s_[1][nf], qa[1], kbf[nf]);
            }
        }

        // ---- per-warp softmax over its 64-key half ----
        const bool needmask = (kb + 63 > qbase + wq);
        uint32_t P2[2][4][4];
#pragma unroll
        for (int mf = 0; mf < 2; mf++) {
            const int gr0 = qbase + wq + mf * 16 + lq;
            const int gr1 = gr0 + 8;
            float mx0 = -CUDART_INF_F, mx1 = -CUDART_INF_F;
#pragma unroll
            for (int nf = 0; nf < 8; nf++) {
                if (needmask) {
                    const int c0 = kb + nf * 8 + 2 * lr;
                    if (c0 > gr0)     s_[mf][nf][0] = -CUDART_INF_F;
                    if (c0 + 1 > gr0) s_[mf][nf][1] = -CUDART_INF_F;
                    if (c0 > gr1)     s_[mf][nf][2] = -CUDART_INF_F;
                    if (c0 + 1 > gr1) s_[mf][nf][3] = -CUDART_INF_F;
                }
                mx0 = fmaxf(mx0, fmaxf(s_[mf][nf][0], s_[mf][nf][1]));
                mx1 = fmaxf(mx1, fmaxf(s_[mf][nf][2], s_[mf][nf][3]));
            }
#pragma unroll
            for (int msk = 1; msk < 4; msk <<= 1) {
                mx0 = fmaxf(mx0, __shfl_xor_sync(0xffffffffu, mx0, msk));
                mx1 = fmaxf(mx1, __shfl_xor_sync(0xffffffffu, mx1, msk));
            }
            const float nm0 = fmaxf(mm[mf][0], mx0);
            const float nm1 = fmaxf(mm[mf][1], mx1);
            const float al0 = __expf(mm[mf][0] - nm0);
            const float al1 = __expf(mm[mf][1] - nm1);
            mm[mf][0] = nm0; mm[mf][1] = nm1;

            float sm0 = 0.f, sm1 = 0.f;
#pragma unroll
            for (int nf = 0; nf < 8; nf++) {
                float p0 = __expf(s_[mf][nf][0] - nm0);
                float p1 = __expf(s_[mf][nf][1] - nm0);
                float p2 = __expf(s_[mf][nf][2] - nm1);
                float p3 = __expf(s_[mf][nf][3] - nm1);
                sm0 += p0 + p1; sm1 += p2 + p3;
                s_[mf][nf][0] = p0; s_[mf][nf][1] = p1;
                s_[mf][nf][2] = p2; s_[mf][nf][3] = p3;
            }
#pragma unroll
            for (int msk = 1; msk < 4; msk <<= 1) {
                sm0 += __shfl_xor_sync(0xffffffffu, sm0, msk);
                sm1 += __shfl_xor_sync(0xffffffffu, sm1, msk);
            }
            ll[mf][0] = ll[mf][0] * al0 + sm0;
            ll[mf][1] = ll[mf][1] * al1 + sm1;
#pragma unroll
            for (int nf = 0; nf < 16; nf++) {
                o[mf][nf][0] *= al0; o[mf][nf][1] *= al0;
                o[mf][nf][2] *= al1; o[mf][nf][3] *= al1;
            }
#pragma unroll
            for (int kf = 0; kf < 4; kf++) {
                P2[mf][kf][0] = packh2(s_[mf][2 * kf][0],     s_[mf][2 * kf][1]);
                P2[mf][kf][1] = packh2(s_[mf][2 * kf][2],     s_[mf][2 * kf][3]);
                P2[mf][kf][2] = packh2(s_[mf][2 * kf + 1][0], s_[mf][2 * kf + 1][1]);
                P2[mf][kf][3] = packh2(s_[mf][2 * kf + 1][2], s_[mf][2 * kf + 1][3]);
            }
        }

        // ---- O += P @ V ----
#pragma unroll
        for (int kf = 0; kf < 4; kf++) {
            uint32_t vbf[16][2];
#pragma unroll
            for (int p = 0; p < 8; p++)
                LDSM_X4(vbf[2 * p][0], vbf[2 * p][1], vbf[2 * p + 1][0], vbf[2 * p + 1][1],
                        vsb + vb_lane + p * (16 * 272) + kf * 32);
#pragma unroll
            for (int nf = 0; nf < 16; nf++) {
                mma_f16(o[0][nf], P2[0][kf], vbf[nf]);
                mma_f16(o[1][nf], P2[1][kf], vbf[nf]);
            }
        }
    }

    // ---- merge key-halves: wc=1 publishes (fp32), wc=0 combines + stores ----
    float* Ox = (float*)smc;                 // [4][32][132] fp32
    float* St = Ox + 4 * 32 * 132;           // [128][2]
    __syncthreads();
    if (wc == 1) {
        float* ob = Ox + wr * 32 * 132;
#pragma unroll
        for (int mf = 0; mf < 2; mf++) {
            const int row0 = mf * 16 + lq;
#pragma unroll
            for (int nf = 0; nf < 16; nf++) {
                const int col = nf * 8 + 2 * lr;
                *(float2*)&ob[row0 * 132 + col]       = make_float2(o[mf][nf][0], o[mf][nf][1]);
                *(float2*)&ob[(row0 + 8) * 132 + col] = make_float2(o[mf][nf][2], o[mf][nf][3]);
            }
            if (lr == 0) {
                float* st = St + (wr * 32 + row0) * 2;
                st[0] = mm[mf][0]; st[1] = ll[mf][0];
                st[16] = mm[mf][1]; st[17] = ll[mf][1];
            }
        }
    }
    __syncthreads();
    if (wc == 0) {
        const float* ob = Ox + wr * 32 * 132;
#pragma unroll
        for (int mf = 0; mf < 2; mf++) {
            const int row0 = mf * 16 + lq;
            const float* st = St + (wr * 32 + row0) * 2;
            const float mo0 = st[0],  lo0 = st[1];
            const float mo1 = st[16], lo1 = st[17];
            const float M0 = fmaxf(mm[mf][0], mo0);
            const float M1 = fmaxf(mm[mf][1], mo1);
            const float as0 = __expf(mm[mf][0] - M0), ao0 = __expf(mo0 - M0);
            const float as1 = __expf(mm[mf][1] - M1), ao1 = __expf(mo1 - M1);
            const float inv0 = 1.f / (ll[mf][0] * as0 + lo0 * ao0);
            const float inv1 = 1.f / (ll[mf][1] * as1 + lo1 * ao1);
            const float fs0 = as0 * inv0, fo0 = ao0 * inv0;
            const float fs1 = as1 * inv1, fo1 = ao1 * inv1;
            const size_t r0 = rowbase + qbase + wq + row0;
            const size_t r1 = r0 + 8;
#pragma unroll
            for (int nf = 0; nf < 16; nf++) {
                const int col = nf * 8 + 2 * lr;
                float2 q0 = *(const float2*)&ob[row0 * 132 + col];
                float2 q1 = *(const float2*)&ob[(row0 + 8) * 132 + col];
                *(uint32_t*)(C + r0 * 2048 + qcol + col) =
                    packh2(o[mf][nf][0] * fs0 + q0.x * fo0,
                           o[mf][nf][1] * fs0 + q0.y * fo0);
                *(uint32_t*)(C + r1 * 2048 + qcol + col) =
                    packh2(o[mf][nf][2] * fs1 + q1.x * fo1,
                           o[mf][nf][3] * fs1 + q1.y * fo1);
            }
        }
    }
#undef KV_LOAD
}

// ---------------------------------------------------------------------------
extern "C" void kernel_launch(void* const* d_in, const int* in_sizes, int n_in,
                              void* d_out, int out_size)
{
    const float* x  = (const float*)d_in[0];
    const float* Wq = (const float*)d_in[1];
    const float* Wk = (const float*)d_in[2];
    const float* Wv = (const float*)d_in[3];
    const float* Wo = (const float*)d_in[4];
    const float* bo = (const float*)d_in[5];

    const int M = in_sizes[0] / D_IN;   // 4096
    const int B = M / SEQ;              // 2

    __half *Xh, *WqT, *WkT, *WvT, *WoT, *Qh, *Kh, *Vt, *Ch;
    cudaGetSymbolAddress((void**)&Xh,  g_Xh);
    cudaGetSymbolAddress((void**)&WqT, g_WqT);
    cudaGetSymbolAddress((void**)&WkT, g_WkT);
    cudaGetSymbolAddress((void**)&WvT, g_WvT);
    cudaGetSymbolAddress((void**)&WoT, g_WoT);
    cudaGetSymbolAddress((void**)&Qh,  g_Qh);
    cudaGetSymbolAddress((void**)&Kh,  g_Kh);
    cudaGetSymbolAddress((void**)&Vt,  g_Vt);
    cudaGetSymbolAddress((void**)&Ch,  g_Ch);

    cudaFuncSetAttribute(gemm_h<true>,
                         cudaFuncAttributeMaxDynamicSharedMemorySize, GEMM_SMEM);
    cudaFuncSetAttribute(gemm_h<false>,
                         cudaFuncAttributeMaxDynamicSharedMemorySize, GEMM_SMEM);
    cudaFuncSetAttribute(attn_h,
                         cudaFuncAttributeMaxDynamicSharedMemorySize, ATTN_SMEM);

    // prepass: fp16 conversions + paired weight transposes
    cvt_x<<<(M * D_IN) / 1024, 256>>>(x, Xh);
    transpose2_h<<<dim3(64, 64, 2), dim3(32, 8)>>>(Wq, WqT, Wo, WoT, 2048, 2048);
    transpose2_h<<<dim3(16, 64, 2), dim3(32, 8)>>>(Wk, WkT, Wv, WvT, 2048, 512);

    // fused QKV projection: N = 2048 (Q) + 512 (K) + 512 (V^T) = 3072
    gemm_h<true><<<dim3(24, M / 128), 256, GEMM_SMEM>>>(
        Xh, WqT, WkT, WvT, Qh, Kh, Vt, nullptr, nullptr);

    attn_h<<<dim3(SEQ / 128, B * 16), 256, ATTN_SMEM>>>(Qh, Kh, Vt, Ch);

    // output projection + bias (fp32 out)
    gemm_h<false><<<dim3(16, M / 128), 256, GEMM_SMEM>>>(
        Ch, WoT, nullptr, nullptr, nullptr, nullptr, nullptr, (float*)d_out, bo);
}

// round 13
// speedup vs baseline: 1.5484x; 1.0114x over previous
#include <cuda_runtime.h>
#include <cuda_fp16.h>
#include <math_constants.h>
#include <cstdint>

#define D_IN   2048
#define D_OUT  2048
#define HD     128
#define NG     4
#define HPG    4
#define SEQ    2048
#define GK     2048      /* K dim of every GEMM */

// ---------------- scratch (no cudaMalloc allowed) ----------------
__device__ __half g_Xh [4096 * 2048];   // x, fp16
__device__ __half g_WqT[2048 * 2048];   // Wq^T [n][k] fp16
__device__ __half g_WkT[512  * 2048];
__device__ __half g_WvT[512  * 2048];
__device__ __half g_WoT[2048 * 2048];
__device__ __half g_Qh [4096 * 2048];   // q proj, scaled by SCALE*log2e, fp16
__device__ __half g_Kh [4096 * 512];    // k proj fp16 [seq][gdim]
__device__ __half g_Vt [8 * 128 * 2048];// v proj TRANSPOSED [b*g][dim][seq]
__device__ __half g_Ch [4096 * 2048];   // ctx fp16

// ---------------- helpers ----------------
__device__ __forceinline__ void mma_f16(float* d, const uint32_t* a, const uint32_t* b) {
    asm volatile(
        "mma.sync.aligned.m16n8k16.row.col.f32.f16.f16.f32 "
        "{%0,%1,%2,%3}, {%4,%5,%6,%7}, {%8,%9}, {%0,%1,%2,%3};"
        : "+f"(d[0]), "+f"(d[1]), "+f"(d[2]), "+f"(d[3])
        : "r"(a[0]), "r"(a[1]), "r"(a[2]), "r"(a[3]), "r"(b[0]), "r"(b[1]));
}
__device__ __forceinline__ uint32_t smem_u32(const void* p) {
    uint32_t a;
    asm("{ .reg .u64 t; cvta.to.shared.u64 t, %1; cvt.u32.u64 %0, t; }" : "=r"(a) : "l"(p));
    return a;
}
__device__ __forceinline__ uint32_t packh2(float x, float y) {
    __half2 h = __floats2half2_rn(x, y);
    return *(uint32_t*)&h;
}
__device__ __forceinline__ float ex2f(float x) {   // bare exp2 (log2-domain softmax)
    float y;
    asm("ex2.approx.f32 %0, %1;" : "=f"(y) : "f"(x));
    return y;
}
#define LDSM_X4(r0, r1, r2, r3, addr) \
    asm volatile("ldmatrix.sync.aligned.m8n8.x4.shared.b16 {%0,%1,%2,%3}, [%4];" \
        : "=r"(r0), "=r"(r1), "=r"(r2), "=r"(r3) : "r"(addr))
#define CP_ASYNC16(dst, src) \
    asm volatile("cp.async.cg.shared.global [%0], [%1], 16;" :: "r"(dst), "l"(src) : "memory")
#define CP_COMMIT() asm volatile("cp.async.commit_group;" ::: "memory")
#define CP_WAIT0()  asm volatile("cp.async.wait_group 0;" ::: "memory")
#define CP_WAIT1()  asm volatile("cp.async.wait_group 1;" ::: "memory")

#define SCALE_L2E 0.12751882374877618f   /* (1/sqrt(128)) * log2(e) */

// ---------------- prepass ----------------
__global__ void cvt_x(const float* __restrict__ in, __half* __restrict__ out) {
    size_t i = ((size_t)blockIdx.x * blockDim.x + threadIdx.x) * 4;
    float4 v = *(const float4*)(in + i);
    uint2 o;
    o.x = packh2(v.x, v.y);
    o.y = packh2(v.z, v.w);
    *(uint2*)(out + i) = o;
}

// paired transpose: z=0 -> (W0,Wt0), z=1 -> (W1,Wt1).  W [K][N] -> Wt [N][K] fp16
__global__ void transpose2_h(const float* __restrict__ W0, __half* __restrict__ Wt0,
                             const float* __restrict__ W1, __half* __restrict__ Wt1,
                             int K, int N) {
    __shared__ float t[32][33];
    const float* W = blockIdx.z ? W1 : W0;
    __half* Wt = blockIdx.z ? Wt1 : Wt0;
    int x = blockIdx.x * 32 + threadIdx.x;   // n
    int y = blockIdx.y * 32 + threadIdx.y;   // k
#pragma unroll
    for (int i = 0; i < 32; i += 8)
        t[threadIdx.y + i][threadIdx.x] = W[(size_t)(y + i) * N + x];
    __syncthreads();
    int x2 = blockIdx.y * 32 + threadIdx.x;  // k
    int y2 = blockIdx.x * 32 + threadIdx.y;  // n
#pragma unroll
    for (int i = 0; i < 32; i += 8)
        Wt[(size_t)(y2 + i) * K + x2] = __float2half_rn(t[threadIdx.x][threadIdx.y + i]);
}

// -- fp16 mma GEMM: CTA 128x128, 8 warps @ 32x64, BK=64, 3-stage, 2 CTA/SM --
// Single barrier per K-iteration (top barrier alone orders the stage reuse).
#define GLDB 144                          /* smem row stride bytes (64h + pad) */
#define GAS_B (128 * GLDB)                /* 18432 B */
#define GSTG_B (2 * GAS_B)                /* 36864 B */
#define GEMM_SMEM (3 * GSTG_B)            /* 110592 B */

template <bool PROJ>
__global__ __launch_bounds__(256, 2) void gemm_h(
    const __half* __restrict__ A,
    const __half* __restrict__ B0, const __half* __restrict__ B1,
    const __half* __restrict__ B2,
    __half* __restrict__ Qo, __half* __restrict__ Ko, __half* __restrict__ Vo,
    float* __restrict__ Co, const float* __restrict__ bias)
{
    extern __shared__ char smc[];
    const int tid = threadIdx.x;
    const int wid = tid >> 5, l = tid & 31;
    const int lq = l >> 2, lr = l & 3;
    const int m0 = blockIdx.y * 128;
    const int n0 = blockIdx.x * 128;
    const int wm = (wid & 3) * 32, wn = (wid >> 2) * 64;
    const uint32_t smb = smem_u32(smc);

    const __half* Bp;
    if (PROJ) {
        if (n0 < 2048)      Bp = B0 + (size_t)n0 * GK;
        else if (n0 < 2560) Bp = B1 + (size_t)(n0 - 2048) * GK;
        else                Bp = B2 + (size_t)(n0 - 2560) * GK;
    } else Bp = B0 + (size_t)n0 * GK;

    float acc[2][8][4];
#pragma unroll
    for (int i = 0; i < 2; i++)
#pragma unroll
        for (int j = 0; j < 8; j++)
#pragma unroll
            for (int r = 0; r < 4; r++) acc[i][j][r] = 0.f;

    const uint32_t a_lane = (uint32_t)((wm + (l & 15)) * GLDB + (l >> 4) * 16);
    const uint32_t b_lane = (uint32_t)((wn + (l & 7) + ((l >> 4) << 3)) * GLDB
                                       + ((l >> 3) & 1) * 16);

#define G_LOAD(s, kc) do {                                                        \
        uint32_t _ab = smb + (s) * GSTG_B;                                        \
        uint32_t _bb = _ab + GAS_B;                                               \
        _Pragma("unroll")                                                         \
        for (int _i = 0; _i < 4; _i++) {                                          \
            int _e = tid + _i * 256, _r = _e >> 3, _ch = _e & 7;                  \
            CP_ASYNC16(_ab + _r * GLDB + _ch * 16,                                \
                (const void*)(A + (size_t)(m0 + _r) * GK + (kc) * 64 + _ch * 8)); \
            CP_ASYNC16(_bb + _r * GLDB + _ch * 16,                                \
                (const void*)(Bp + (size_t)_r * GK + (kc) * 64 + _ch * 8));       \
        }                                                                         \
    } while (0)

    G_LOAD(0, 0); CP_COMMIT();
    G_LOAD(1, 1); CP_COMMIT();

    const int kiters = GK / 64;   // 32
    for (int it = 0; it < kiters; it++) {
        CP_WAIT1();
        __syncthreads();          // orders: stage (it%3) ready; all warps done with it-1
        if (it + 2 < kiters) { G_LOAD((it + 2) % 3, it + 2); CP_COMMIT(); }

        const uint32_t abase = smb + (it % 3) * GSTG_B + a_lane;
        const uint32_t bbase = smb + (it % 3) * GSTG_B + GAS_B + b_lane;

#pragma unroll
        for (int ks = 0; ks < 4; ks++) {
            uint32_t af[2][4], bf[8][2];
#pragma unroll
            for (int mf = 0; mf < 2; mf++)
                LDSM_X4(af[mf][0], af[mf][1], af[mf][2], af[mf][3],
                        abase + mf * (16 * GLDB) + ks * 32);
#pragma unroll
            for (int p = 0; p < 4; p++)
                LDSM_X4(bf[2 * p][0], bf[2 * p][1], bf[2 * p + 1][0], bf[2 * p + 1][1],
                        bbase + p * (16 * GLDB) + ks * 32);
#pragma unroll
            for (int mf = 0; mf < 2; mf++)
#pragma unroll
                for (int nf = 0; nf < 8; nf++)
                    mma_f16(acc[mf][nf], af[mf], bf[nf]);
        }
        // no trailing barrier: next iteration's top barrier provides the ordering
    }

    // epilogue
#pragma unroll
    for (int mf = 0; mf < 2; mf++) {
        const int row = m0 + wm + mf * 16 + lq;
#pragma unroll
        for (int nf = 0; nf < 8; nf++) {
            const int col = wn + nf * 8 + 2 * lr;
            const float c0 = acc[mf][nf][0], c1 = acc[mf][nf][1];
            const float c2 = acc[mf][nf][2], c3 = acc[mf][nf][3];
            if (!PROJ) {
                float2 b = *(const float2*)(bias + n0 + col);
                *(float2*)(Co + (size_t)row * 2048 + n0 + col) =
                    make_float2(c0 + b.x, c1 + b.y);
                *(float2*)(Co + (size_t)(row + 8) * 2048 + n0 + col) =
                    make_float2(c2 + b.x, c3 + b.y);
            } else if (n0 < 2048) {
                *(uint32_t*)(Qo + (size_t)row * 2048 + n0 + col) =
                    packh2(c0 * SCALE_L2E, c1 * SCALE_L2E);
                *(uint32_t*)(Qo + (size_t)(row + 8) * 2048 + n0 + col) =
                    packh2(c2 * SCALE_L2E, c3 * SCALE_L2E);
            } else if (n0 < 2560) {
                const int kc = n0 - 2048 + col;
                *(uint32_t*)(Ko + (size_t)row * 512 + kc) = packh2(c0, c1);
                *(uint32_t*)(Ko + (size_t)(row + 8) * 512 + kc) = packh2(c2, c3);
            } else {
                const int vd = n0 - 2560 + col;
                const int gi = vd >> 7, d = vd & 127;
                const int bi = row >> 11, s = row & 2047;
                __half* vb = Vo + ((size_t)(bi * NG + gi) * 128 + d) * 2048;
                vb[s]            = __float2half_rn(c0);
                vb[2048 + s]     = __float2half_rn(c1);
                vb[s + 8]        = __float2half_rn(c2);
                vb[2048 + s + 8] = __float2half_rn(c3);
            }
        }
    }
#undef G_LOAD
}

// -------- fp16 mma flash-attention: split-softmax 4x2 warps, 128-key tiles --
// log2-domain softmax: scores pre-scaled by log2e, bare ex2 everywhere.
#define HLD 136
#define QS_B (128 * 272)
#define KS_B (128 * 272)
#define VS_B (128 * 272)
#define ATTN_SMEM (QS_B + 2 * KS_B + 2 * VS_B)   /* 174080 B */

__global__ __launch_bounds__(256, 1) void attn_h(
    const __half* __restrict__ Q, const __half* __restrict__ K,
    const __half* __restrict__ VT, __half* __restrict__ C)
{
    extern __shared__ char smc[];
    const int tid = threadIdx.x;
    const int wid = tid >> 5, l = tid & 31;
    const int lq = l >> 2, lr = l & 3;
    const int wr = wid >> 1, wc = wid & 1;
    const int wq = wr * 32;
    const int koff = wc * 64;

    const int qc = gridDim.x - 1 - blockIdx.x;   // long CTAs first
    const int hh = blockIdx.y;
    const int bi = hh >> 4;
    const int gi = (hh >> 2) & 3;
    const int hi = hh & 3;
    const int qcol = (gi * HPG + hi) * HD;
    const int kcol = gi * HD;
    const size_t rowbase = (size_t)bi * SEQ;
    const int qbase = qc * 128;
    const uint32_t smb = smem_u32(smc);
    const __half* vtb = VT + (size_t)(bi * NG + gi) * 128 * 2048;

    const uint32_t qa_lane = (uint32_t)((wq + (l & 15)) * 272 + (l >> 4) * 16);
    const uint32_t kb_lane = (uint32_t)((koff + (l & 7) + ((l >> 4) << 3)) * 272
                                        + ((l >> 3) & 1) * 16);
    const uint32_t vb_lane = (uint32_t)(((l & 7) + ((l >> 4) << 3)) * 272
                                        + ((l >> 3) & 1) * 16 + koff * 2);

    // ---- Q tile [128 q][128 d] fp16 ----
#pragma unroll
    for (int u = 0; u < 8; u++) {
        int e = tid + u * 256, r = e >> 4, ch = e & 15;
        CP_ASYNC16(smb + r * 272 + ch * 16,
                   (const void*)(Q + (rowbase + qbase + r) * 2048 + qcol + ch * 8));
    }

    float o[2][16][4];
#pragma unroll
    for (int mf = 0; mf < 2; mf++)
#pragma unroll
        for (int i = 0; i < 16; i++)
#pragma unroll
            for (int r = 0; r < 4; r++) o[mf][i][r] = 0.f;
    float mm[2][2], ll[2][2];
#pragma unroll
    for (int mf = 0; mf < 2; mf++) {
        mm[mf][0] = -CUDART_INF_F; mm[mf][1] = -CUDART_INF_F;
        ll[mf][0] = 0.f; ll[mf][1] = 0.f;
    }

    const int jmax = qc;

#define KV_LOAD(ss, jj) do {                                                     \
        uint32_t _kb = smb + QS_B + (ss) * KS_B;                                  \
        uint32_t _vb = smb + QS_B + 2 * KS_B + (ss) * VS_B;                       \
        _Pragma("unroll")                                                         \
        for (int _u = 0; _u < 8; _u++) {                                          \
            int _e = tid + _u * 256, _r = _e >> 4, _ch = _e & 15;                 \
            CP_ASYNC16(_kb + _r * 272 + _ch * 16,                                 \
                (const void*)(K + (rowbase + (jj) * 128 + _r) * 512 + kcol + _ch * 8)); \
            CP_ASYNC16(_vb + _r * 272 + _ch * 16,                                 \
                (const void*)(vtb + (size_t)_r * 2048 + (jj) * 128 + _ch * 8));   \
        }                                                                         \
    } while (0)

    KV_LOAD(0, 0); CP_COMMIT();

    for (int j = 0; j <= jmax; j++) {
        CP_WAIT0();
        __syncthreads();
        if (j < jmax) { KV_LOAD((j + 1) & 1, j + 1); CP_COMMIT(); }

        const int st = j & 1;
        const uint32_t ksb = smb + QS_B + st * KS_B;
        const uint32_t vsb = smb + QS_B + 2 * KS_B + st * VS_B;
        const int kb = j * 128 + koff;
        if (kb > qbase + wq + 31) continue;

        // ---- S = Q @ K^T : 32 q x 64 keys (scores already in log2 domain) ----
        float s_[2][8][4];
#pragma unroll
        for (int mf = 0; mf < 2; mf++)
#pragma unroll
            for (int nf = 0; nf < 8; nf++)
#pragma unroll
                for (int r = 0; r < 4; r++) s_[mf][nf][r] = 0.f;

#pragma unroll
        for (int kf = 0; kf < 8; kf++) {
            uint32_t qa[2][4], kbf[8][2];
#pragma unroll
            for (int mf = 0; mf < 2; mf++)
                LDSM_X4(qa[mf][0], qa[mf][1], qa[mf][2], qa[mf][3],
                        smb + qa_lane + mf * (16 * 272) + kf * 32);
#pragma unroll
            for (int p = 0; p < 4; p++)
                LDSM_X4(kbf[2 * p][0], kbf[2 * p][1], kbf[2 * p + 1][0], kbf[2 * p + 1][1],
                        ksb + kb_lane + p * (16 * 272) + kf * 32);
#pragma unroll
            for (int nf = 0; nf < 8; nf++) {
                mma_f16(s_[0][nf], qa[0], kbf[nf]);
                mma_f16(s_[1][nf], qa[1], kbf[nf]);
            }
        }

        // ---- per-warp softmax (log2 domain, bare ex2) ----
        const bool needmask = (kb + 63 > qbase + wq);
        uint32_t P2[2][4][4];
#pragma unroll
        for (int mf = 0; mf < 2; mf++) {
            const int gr0 = qbase + wq + mf * 16 + lq;
            const int gr1 = gr0 + 8;
            float mx0 = -CUDART_INF_F, mx1 = -CUDART_INF_F;
#pragma unroll
            for (int nf = 0; nf < 8; nf++) {
                if (needmask) {
                    const int c0 = kb + nf * 8 + 2 * lr;
                    if (c0 > gr0)     s_[mf][nf][0] = -CUDART_INF_F;
                    if (c0 + 1 > gr0) s_[mf][nf][1] = -CUDART_INF_F;
                    if (c0 > gr1)     s_[mf][nf][2] = -CUDART_INF_F;
                    if (c0 + 1 > gr1) s_[mf][nf][3] = -CUDART_INF_F;
                }
                mx0 = fmaxf(mx0, fmaxf(s_[mf][nf][0], s_[mf][nf][1]));
                mx1 = fmaxf(mx1, fmaxf(s_[mf][nf][2], s_[mf][nf][3]));
            }
#pragma unroll
            for (int msk = 1; msk < 4; msk <<= 1) {
                mx0 = fmaxf(mx0, __shfl_xor_sync(0xffffffffu, mx0, msk));
                mx1 = fmaxf(mx1, __shfl_xor_sync(0xffffffffu, mx1, msk));
            }
            const float nm0 = fmaxf(mm[mf][0], mx0);
            const float nm1 = fmaxf(mm[mf][1], mx1);
            const float al0 = ex2f(mm[mf][0] - nm0);
            const float al1 = ex2f(mm[mf][1] - nm1);
            mm[mf][0] = nm0; mm[mf][1] = nm1;

            float sm0 = 0.f, sm1 = 0.f;
#pragma unroll
            for (int nf = 0; nf < 8; nf++) {
                float p0 = ex2f(s_[mf][nf][0] - nm0);
                float p1 = ex2f(s_[mf][nf][1] - nm0);
                float p2 = ex2f(s_[mf][nf][2] - nm1);
                float p3 = ex2f(s_[mf][nf][3] - nm1);
                sm0 += p0 + p1; sm1 += p2 + p3;
                s_[mf][nf][0] = p0; s_[mf][nf][1] = p1;
                s_[mf][nf][2] = p2; s_[mf][nf][3] = p3;
            }
#pragma unroll
            for (int msk = 1; msk < 4; msk <<= 1) {
                sm0 += __shfl_xor_sync(0xffffffffu, sm0, msk);
                sm1 += __shfl_xor_sync(0xffffffffu, sm1, msk);
            }
            ll[mf][0] = ll[mf][0] * al0 + sm0;
            ll[mf][1] = ll[mf][1] * al1 + sm1;
#pragma unroll
            for (int nf = 0; nf < 16; nf++) {
                o[mf][nf][0] *= al0; o[mf][nf][1] *= al0;
                o[mf][nf][2] *= al1; o[mf][nf][3] *= al1;
            }
#pragma unroll
            for (int kf = 0; kf < 4; kf++) {
                P2[mf][kf][0] = packh2(s_[mf][2 * kf][0],     s_[mf][2 * kf][1]);
                P2[mf][kf][1] = packh2(s_[mf][2 * kf][2],     s_[mf][2 * kf][3]);
                P2[mf][kf][2] = packh2(s_[mf][2 * kf + 1][0], s_[mf][2 * kf + 1][1]);
                P2[mf][kf][3] = packh2(s_[mf][2 * kf + 1][2], s_[mf][2 * kf + 1][3]);
            }
        }

        // ---- O += P @ V ----
#pragma unroll
        for (int kf = 0; kf < 4; kf++) {
            uint32_t vbf[16][2];
#pragma unroll
            for (int p = 0; p < 8; p++)
                LDSM_X4(vbf[2 * p][0], vbf[2 * p][1], vbf[2 * p + 1][0], vbf[2 * p + 1][1],
                        vsb + vb_lane + p * (16 * 272) + kf * 32);
#pragma unroll
            for (int nf = 0; nf < 16; nf++) {
                mma_f16(o[0][nf], P2[0][kf], vbf[nf]);
                mma_f16(o[1][nf], P2[1][kf], vbf[nf]);
            }
        }
    }

    // ---- merge key-halves: wc=1 publishes (fp32), wc=0 combines + stores ----
    float* Ox = (float*)smc;                 // [4][32][132] fp32
    float* St = Ox + 4 * 32 * 132;           // [128][2]
    __syncthreads();
    if (wc == 1) {
        float* ob = Ox + wr * 32 * 132;
#pragma unroll
        for (int mf = 0; mf < 2; mf++) {
            const int row0 = mf * 16 + lq;
#pragma unroll
            for (int nf = 0; nf < 16; nf++) {
                const int col = nf * 8 + 2 * lr;
                *(float2*)&ob[row0 * 132 + col]       = make_float2(o[mf][nf][0], o[mf][nf][1]);
                *(float2*)&ob[(row0 + 8) * 132 + col] = make_float2(o[mf][nf][2], o[mf][nf][3]);
            }
            if (lr == 0) {
                float* st = St + (wr * 32 + row0) * 2;
                st[0] = mm[mf][0]; st[1] = ll[mf][0];
                st[16] = mm[mf][1]; st[17] = ll[mf][1];
            }
        }
    }
    __syncthreads();
    if (wc == 0) {
        const float* ob = Ox + wr * 32 * 132;
#pragma unroll
        for (int mf = 0; mf < 2; mf++) {
            const int row0 = mf * 16 + lq;
            const float* st = St + (wr * 32 + row0) * 2;
            const float mo0 = st[0],  lo0 = st[1];
            const float mo1 = st[16], lo1 = st[17];
            const float M0 = fmaxf(mm[mf][0], mo0);
            const float M1 = fmaxf(mm[mf][1], mo1);
            const float as0 = ex2f(mm[mf][0] - M0), ao0 = ex2f(mo0 - M0);
            const float as1 = ex2f(mm[mf][1] - M1), ao1 = ex2f(mo1 - M1);
            const float inv0 = 1.f / (ll[mf][0] * as0 + lo0 * ao0);
            const float inv1 = 1.f / (ll[mf][1] * as1 + lo1 * ao1);
            const float fs0 = as0 * inv0, fo0 = ao0 * inv0;
            const float fs1 = as1 * inv1, fo1 = ao1 * inv1;
            const size_t r0 = rowbase + qbase + wq + row0;
            const size_t r1 = r0 + 8;
#pragma unroll
            for (int nf = 0; nf < 16; nf++) {
                const int col = nf * 8 + 2 * lr;
                float2 q0 = *(const float2*)&ob[row0 * 132 + col];
                float2 q1 = *(const float2*)&ob[(row0 + 8) * 132 + col];
                *(uint32_t*)(C + r0 * 2048 + qcol + col) =
                    packh2(o[mf][nf][0] * fs0 + q0.x * fo0,
                           o[mf][nf][1] * fs0 + q0.y * fo0);
                *(uint32_t*)(C + r1 * 2048 + qcol + col) =
                    packh2(o[mf][nf][2] * fs1 + q1.x * fo1,
                           o[mf][nf][3] * fs1 + q1.y * fo1);
            }
        }
    }
#undef KV_LOAD
}

// ---------------------------------------------------------------------------
extern "C" void kernel_launch(void* const* d_in, const int* in_sizes, int n_in,
                              void* d_out, int out_size)
{
    const float* x  = (const float*)d_in[0];
    const float* Wq = (const float*)d_in[1];
    const float* Wk = (const float*)d_in[2];
    const float* Wv = (const float*)d_in[3];
    const float* Wo = (const float*)d_in[4];
    const float* bo = (const float*)d_in[5];

    const int M = in_sizes[0] / D_IN;   // 4096
    const int B = M / SEQ;              // 2

    __half *Xh, *WqT, *WkT, *WvT, *WoT, *Qh, *Kh, *Vt, *Ch;
    cudaGetSymbolAddress((void**)&Xh,  g_Xh);
    cudaGetSymbolAddress((void**)&WqT, g_WqT);
    cudaGetSymbolAddress((void**)&WkT, g_WkT);
    cudaGetSymbolAddress((void**)&WvT, g_WvT);
    cudaGetSymbolAddress((void**)&WoT, g_WoT);
    cudaGetSymbolAddress((void**)&Qh,  g_Qh);
    cudaGetSymbolAddress((void**)&Kh,  g_Kh);
    cudaGetSymbolAddress((void**)&Vt,  g_Vt);
    cudaGetSymbolAddress((void**)&Ch,  g_Ch);

    cudaFuncSetAttribute(gemm_h<true>,
                         cudaFuncAttributeMaxDynamicSharedMemorySize, GEMM_SMEM);
    cudaFuncSetAttribute(gemm_h<false>,
                         cudaFuncAttributeMaxDynamicSharedMemorySize, GEMM_SMEM);
    cudaFuncSetAttribute(attn_h,
                         cudaFuncAttributeMaxDynamicSharedMemorySize, ATTN_SMEM);

    // prepass: fp16 conversions + paired weight transposes
    cvt_x<<<(M * D_IN) / 1024, 256>>>(x, Xh);
    transpose2_h<<<dim3(64, 64, 2), dim3(32, 8)>>>(Wq, WqT, Wo, WoT, 2048, 2048);
    transpose2_h<<<dim3(16, 64, 2), dim3(32, 8)>>>(Wk, WkT, Wv, WvT, 2048, 512);

    // fused QKV projection: N = 2048 (Q) + 512 (K) + 512 (V^T) = 3072
    gemm_h<true><<<dim3(24, M / 128), 256, GEMM_SMEM>>>(
        Xh, WqT, WkT, WvT, Qh, Kh, Vt, nullptr, nullptr);

    attn_h<<<dim3(SEQ / 128, B * 16), 256, ATTN_SMEM>>>(Qh, Kh, Vt, Ch);

    // output projection + bias (fp32 out)
    gemm_h<false><<<dim3(16, M / 128), 256, GEMM_SMEM>>>(
        Ch, WoT, nullptr, nullptr, nullptr, nullptr, nullptr, (float*)d_out, bo);
}

// round 14
// speedup vs baseline: 1.5546x; 1.0040x over previous
#include <cuda_runtime.h>
#include <cuda_fp16.h>
#include <math_constants.h>
#include <cstdint>

#define D_IN   2048
#define D_OUT  2048
#define HD     128
#define NG     4
#define HPG    4
#define SEQ    2048
#define GK     2048      /* K dim of every GEMM */

// ---------------- scratch (no cudaMalloc allowed) ----------------
__device__ __half g_Xh [4096 * 2048];   // x, fp16
__device__ __half g_WqT[2048 * 2048];   // Wq^T [n][k] fp16
__device__ __half g_WkT[512  * 2048];
__device__ __half g_WvT[512  * 2048];
__device__ __half g_WoT[2048 * 2048];
__device__ __half g_Qh [4096 * 2048];   // q proj, scaled by SCALE*log2e, fp16
__device__ __half g_Kh [4096 * 512];    // k proj fp16 [seq][gdim]
__device__ __half g_Vt [8 * 128 * 2048];// v proj TRANSPOSED [b*g][dim][seq]
__device__ __half g_Ch [4096 * 2048];   // ctx fp16

// ---------------- helpers ----------------
__device__ __forceinline__ void mma_f16(float* d, const uint32_t* a, const uint32_t* b) {
    asm volatile(
        "mma.sync.aligned.m16n8k16.row.col.f32.f16.f16.f32 "
        "{%0,%1,%2,%3}, {%4,%5,%6,%7}, {%8,%9}, {%0,%1,%2,%3};"
        : "+f"(d[0]), "+f"(d[1]), "+f"(d[2]), "+f"(d[3])
        : "r"(a[0]), "r"(a[1]), "r"(a[2]), "r"(a[3]), "r"(b[0]), "r"(b[1]));
}
__device__ __forceinline__ uint32_t smem_u32(const void* p) {
    uint32_t a;
    asm("{ .reg .u64 t; cvta.to.shared.u64 t, %1; cvt.u32.u64 %0, t; }" : "=r"(a) : "l"(p));
    return a;
}
__device__ __forceinline__ uint32_t packh2(float x, float y) {
    __half2 h = __floats2half2_rn(x, y);
    return *(uint32_t*)&h;
}
__device__ __forceinline__ float ex2f(float x) {   // bare exp2 (log2-domain softmax)
    float y;
    asm("ex2.approx.f32 %0, %1;" : "=f"(y) : "f"(x));
    return y;
}
__device__ __forceinline__ float rcpf(float x) {
    float y;
    asm("rcp.approx.f32 %0, %1;" : "=f"(y) : "f"(x));
    return y;
}
#define LDSM_X4(r0, r1, r2, r3, addr) \
    asm volatile("ldmatrix.sync.aligned.m8n8.x4.shared.b16 {%0,%1,%2,%3}, [%4];" \
        : "=r"(r0), "=r"(r1), "=r"(r2), "=r"(r3) : "r"(addr))
#define CP_ASYNC16(dst, src) \
    asm volatile("cp.async.cg.shared.global [%0], [%1], 16;" :: "r"(dst), "l"(src) : "memory")
#define CP_COMMIT() asm volatile("cp.async.commit_group;" ::: "memory")
#define CP_WAIT0()  asm volatile("cp.async.wait_group 0;" ::: "memory")
#define CP_WAIT1()  asm volatile("cp.async.wait_group 1;" ::: "memory")

#define SCALE_L2E 0.12751882374877618f   /* (1/sqrt(128)) * log2(e) */

// ---------------- prepass ----------------
__global__ void cvt_x(const float* __restrict__ in, __half* __restrict__ out) {
    size_t i = ((size_t)blockIdx.x * blockDim.x + threadIdx.x) * 4;
    float4 v = *(const float4*)(in + i);
    uint2 o;
    o.x = packh2(v.x, v.y);
    o.y = packh2(v.z, v.w);
    *(uint2*)(out + i) = o;
}

// paired transpose: z=0 -> (W0,Wt0), z=1 -> (W1,Wt1).  W [K][N] -> Wt [N][K] fp16
__global__ void transpose2_h(const float* __restrict__ W0, __half* __restrict__ Wt0,
                             const float* __restrict__ W1, __half* __restrict__ Wt1,
                             int K, int N) {
    __shared__ float t[32][33];
    const float* W = blockIdx.z ? W1 : W0;
    __half* Wt = blockIdx.z ? Wt1 : Wt0;
    int x = blockIdx.x * 32 + threadIdx.x;   // n
    int y = blockIdx.y * 32 + threadIdx.y;   // k
#pragma unroll
    for (int i = 0; i < 32; i += 8)
        t[threadIdx.y + i][threadIdx.x] = W[(size_t)(y + i) * N + x];
    __syncthreads();
    int x2 = blockIdx.y * 32 + threadIdx.x;  // k
    int y2 = blockIdx.x * 32 + threadIdx.y;  // n
#pragma unroll
    for (int i = 0; i < 32; i += 8)
        Wt[(size_t)(y2 + i) * K + x2] = __float2half_rn(t[threadIdx.x][threadIdx.y + i]);
}

// -- fp16 mma GEMM: CTA 128x128, 8 warps @ 32x64, BK=64, 3-stage, 2 CTA/SM --
// Single barrier per K-iteration. V output staged through smem for coalesced STG.
#define GLDB 144                          /* smem row stride bytes (64h + pad) */
#define GAS_B (128 * GLDB)                /* 18432 B */
#define GSTG_B (2 * GAS_B)                /* 36864 B */
#define GEMM_SMEM (3 * GSTG_B)            /* 110592 B */

template <bool PROJ>
__global__ __launch_bounds__(256, 2) void gemm_h(
    const __half* __restrict__ A,
    const __half* __restrict__ B0, const __half* __restrict__ B1,
    const __half* __restrict__ B2,
    __half* __restrict__ Qo, __half* __restrict__ Ko, __half* __restrict__ Vo,
    float* __restrict__ Co, const float* __restrict__ bias)
{
    extern __shared__ char smc[];
    const int tid = threadIdx.x;
    const int wid = tid >> 5, l = tid & 31;
    const int lq = l >> 2, lr = l & 3;
    const int m0 = blockIdx.y * 128;
    const int n0 = blockIdx.x * 128;
    const int wm = (wid & 3) * 32, wn = (wid >> 2) * 64;
    const uint32_t smb = smem_u32(smc);

    const __half* Bp;
    if (PROJ) {
        if (n0 < 2048)      Bp = B0 + (size_t)n0 * GK;
        else if (n0 < 2560) Bp = B1 + (size_t)(n0 - 2048) * GK;
        else                Bp = B2 + (size_t)(n0 - 2560) * GK;
    } else Bp = B0 + (size_t)n0 * GK;

    float acc[2][8][4];
#pragma unroll
    for (int i = 0; i < 2; i++)
#pragma unroll
        for (int j = 0; j < 8; j++)
#pragma unroll
            for (int r = 0; r < 4; r++) acc[i][j][r] = 0.f;

    const uint32_t a_lane = (uint32_t)((wm + (l & 15)) * GLDB + (l >> 4) * 16);
    const uint32_t b_lane = (uint32_t)((wn + (l & 7) + ((l >> 4) << 3)) * GLDB
                                       + ((l >> 3) & 1) * 16);

#define G_LOAD(s, kc) do {                                                        \
        uint32_t _ab = smb + (s) * GSTG_B;                                        \
        uint32_t _bb = _ab + GAS_B;                                               \
        _Pragma("unroll")                                                         \
        for (int _i = 0; _i < 4; _i++) {                                          \
            int _e = tid + _i * 256, _r = _e >> 3, _ch = _e & 7;                  \
            CP_ASYNC16(_ab + _r * GLDB + _ch * 16,                                \
                (const void*)(A + (size_t)(m0 + _r) * GK + (kc) * 64 + _ch * 8)); \
            CP_ASYNC16(_bb + _r * GLDB + _ch * 16,                                \
                (const void*)(Bp + (size_t)_r * GK + (kc) * 64 + _ch * 8));       \
        }                                                                         \
    } while (0)

    G_LOAD(0, 0); CP_COMMIT();
    G_LOAD(1, 1); CP_COMMIT();

    const int kiters = GK / 64;   // 32
    for (int it = 0; it < kiters; it++) {
        CP_WAIT1();
        __syncthreads();          // orders: stage (it%3) ready; all warps done with it-1
        if (it + 2 < kiters) { G_LOAD((it + 2) % 3, it + 2); CP_COMMIT(); }

        const uint32_t abase = smb + (it % 3) * GSTG_B + a_lane;
        const uint32_t bbase = smb + (it % 3) * GSTG_B + GAS_B + b_lane;

#pragma unroll
        for (int ks = 0; ks < 4; ks++) {
            uint32_t af[2][4], bf[8][2];
#pragma unroll
            for (int mf = 0; mf < 2; mf++)
                LDSM_X4(af[mf][0], af[mf][1], af[mf][2], af[mf][3],
                        abase + mf * (16 * GLDB) + ks * 32);
#pragma unroll
            for (int p = 0; p < 4; p++)
                LDSM_X4(bf[2 * p][0], bf[2 * p][1], bf[2 * p + 1][0], bf[2 * p + 1][1],
                        bbase + p * (16 * GLDB) + ks * 32);
#pragma unroll
            for (int mf = 0; mf < 2; mf++)
#pragma unroll
                for (int nf = 0; nf < 8; nf++)
                    mma_f16(acc[mf][nf], af[mf], bf[nf]);
        }
        // no trailing barrier: next iteration's top barrier provides the ordering
    }

    // epilogue
    const bool isV = PROJ && (n0 >= 2560);
    __half* vs = (__half*)smc;               // V transpose staging [128 dims][136]
    if (isV) __syncthreads();                // all warps done reading smem stages

#pragma unroll
    for (int mf = 0; mf < 2; mf++) {
        const int row = m0 + wm + mf * 16 + lq;
#pragma unroll
        for (int nf = 0; nf < 8; nf++) {
            const int col = wn + nf * 8 + 2 * lr;
            const float c0 = acc[mf][nf][0], c1 = acc[mf][nf][1];
            const float c2 = acc[mf][nf][2], c3 = acc[mf][nf][3];
            if (!PROJ) {
                float2 b = *(const float2*)(bias + n0 + col);
                *(float2*)(Co + (size_t)row * 2048 + n0 + col) =
                    make_float2(c0 + b.x, c1 + b.y);
                *(float2*)(Co + (size_t)(row + 8) * 2048 + n0 + col) =
                    make_float2(c2 + b.x, c3 + b.y);
            } else if (n0 < 2048) {
                *(uint32_t*)(Qo + (size_t)row * 2048 + n0 + col) =
                    packh2(c0 * SCALE_L2E, c1 * SCALE_L2E);
                *(uint32_t*)(Qo + (size_t)(row + 8) * 2048 + n0 + col) =
                    packh2(c2 * SCALE_L2E, c3 * SCALE_L2E);
            } else if (n0 < 2560) {
                const int kc = n0 - 2048 + col;
                *(uint32_t*)(Ko + (size_t)row * 512 + kc) = packh2(c0, c1);
                *(uint32_t*)(Ko + (size_t)(row + 8) * 512 + kc) = packh2(c2, c3);
            } else {
                // stage V into smem transposed: [dim][m]
                const int lrow = wm + mf * 16 + lq;   // local m (0..127)
                vs[(col)     * 136 + lrow]     = __float2half_rn(c0);
                vs[(col + 1) * 136 + lrow]     = __float2half_rn(c1);
                vs[(col)     * 136 + lrow + 8] = __float2half_rn(c2);
                vs[(col + 1) * 136 + lrow + 8] = __float2half_rn(c3);
            }
        }
    }
    if (isV) {
        __syncthreads();
        const int bi = m0 >> 11, s0 = m0 & 2047;
        const int gi = (n0 - 2560) >> 7;
        __half* vb = Vo + (size_t)(bi * NG + gi) * 128 * 2048;
#pragma unroll
        for (int u = 0; u < 8; u++) {
            int i = tid + u * 256;
            int d = i >> 4, ch = i & 15;
            *(uint4*)(vb + (size_t)d * 2048 + s0 + ch * 8) =
                *(const uint4*)(vs + d * 136 + ch * 8);
        }
    }
#undef G_LOAD
}

// -------- fp16 mma flash-attention: split-softmax 4x2 warps, 128-key tiles --
// log2-domain softmax: scores pre-scaled by log2e, bare ex2 everywhere.
#define HLD 136
#define QS_B (128 * 272)
#define KS_B (128 * 272)
#define VS_B (128 * 272)
#define ATTN_SMEM (QS_B + 2 * KS_B + 2 * VS_B)   /* 174080 B */

__global__ __launch_bounds__(256, 1) void attn_h(
    const __half* __restrict__ Q, const __half* __restrict__ K,
    const __half* __restrict__ VT, __half* __restrict__ C)
{
    extern __shared__ char smc[];
    const int tid = threadIdx.x;
    const int wid = tid >> 5, l = tid & 31;
    const int lq = l >> 2, lr = l & 3;
    const int wr = wid >> 1, wc = wid & 1;
    const int wq = wr * 32;
    const int koff = wc * 64;

    const int qc = gridDim.x - 1 - blockIdx.x;   // long CTAs first
    const int hh = blockIdx.y;
    const int bi = hh >> 4;
    const int gi = (hh >> 2) & 3;
    const int hi = hh & 3;
    const int qcol = (gi * HPG + hi) * HD;
    const int kcol = gi * HD;
    const size_t rowbase = (size_t)bi * SEQ;
    const int qbase = qc * 128;
    const uint32_t smb = smem_u32(smc);
    const __half* vtb = VT + (size_t)(bi * NG + gi) * 128 * 2048;

    const uint32_t qa_lane = (uint32_t)((wq + (l & 15)) * 272 + (l >> 4) * 16);
    const uint32_t kb_lane = (uint32_t)((koff + (l & 7) + ((l >> 4) << 3)) * 272
                                        + ((l >> 3) & 1) * 16);
    const uint32_t vb_lane = (uint32_t)(((l & 7) + ((l >> 4) << 3)) * 272
                                        + ((l >> 3) & 1) * 16 + koff * 2);

    // ---- Q tile [128 q][128 d] fp16 ----
#pragma unroll
    for (int u = 0; u < 8; u++) {
        int e = tid + u * 256, r = e >> 4, ch = e & 15;
        CP_ASYNC16(smb + r * 272 + ch * 16,
                   (const void*)(Q + (rowbase + qbase + r) * 2048 + qcol + ch * 8));
    }

    float o[2][16][4];
#pragma unroll
    for (int mf = 0; mf < 2; mf++)
#pragma unroll
        for (int i = 0; i < 16; i++)
#pragma unroll
            for (int r = 0; r < 4; r++) o[mf][i][r] = 0.f;
    float mm[2][2], ll[2][2];
#pragma unroll
    for (int mf = 0; mf < 2; mf++) {
        mm[mf][0] = -CUDART_INF_F; mm[mf][1] = -CUDART_INF_F;
        ll[mf][0] = 0.f; ll[mf][1] = 0.f;
    }

    const int jmax = qc;

#define KV_LOAD(ss, jj) do {                                                     \
        uint32_t _kb = smb + QS_B + (ss) * KS_B;                                  \
        uint32_t _vb = smb + QS_B + 2 * KS_B + (ss) * VS_B;                       \
        _Pragma("unroll")                                                         \
        for (int _u = 0; _u < 8; _u++) {                                          \
            int _e = tid + _u * 256, _r = _e >> 4, _ch = _e & 15;                 \
            CP_ASYNC16(_kb + _r * 272 + _ch * 16,                                 \
                (const void*)(K + (rowbase + (jj) * 128 + _r) * 512 + kcol + _ch * 8)); \
            CP_ASYNC16(_vb + _r * 272 + _ch * 16,                                 \
                (const void*)(vtb + (size_t)_r * 2048 + (jj) * 128 + _ch * 8));   \
        }                                                                         \
    } while (0)

    KV_LOAD(0, 0); CP_COMMIT();

    for (int j = 0; j <= jmax; j++) {
        CP_WAIT0();
        __syncthreads();
        if (j < jmax) { KV_LOAD((j + 1) & 1, j + 1); CP_COMMIT(); }

        const int st = j & 1;
        const uint32_t ksb = smb + QS_B + st * KS_B;
        const uint32_t vsb = smb + QS_B + 2 * KS_B + st * VS_B;
        const int kb = j * 128 + koff;
        if (kb > qbase + wq + 31) continue;

        // ---- S = Q @ K^T : 32 q x 64 keys (scores already in log2 domain) ----
        float s_[2][8][4];
#pragma unroll
        for (int mf = 0; mf < 2; mf++)
#pragma unroll
            for (int nf = 0; nf < 8; nf++)
#pragma unroll
                for (int r = 0; r < 4; r++) s_[mf][nf][r] = 0.f;

#pragma unroll
        for (int kf = 0; kf < 8; kf++) {
            uint32_t qa[2][4], kbf[8][2];
#pragma unroll
            for (int mf = 0; mf < 2; mf++)
                LDSM_X4(qa[mf][0], qa[mf][1], qa[mf][2], qa[mf][3],
                        smb + qa_lane + mf * (16 * 272) + kf * 32);
#pragma unroll
            for (int p = 0; p < 4; p++)
                LDSM_X4(kbf[2 * p][0], kbf[2 * p][1], kbf[2 * p + 1][0], kbf[2 * p + 1][1],
                        ksb + kb_lane + p * (16 * 272) + kf * 32);
#pragma unroll
            for (int nf = 0; nf < 8; nf++) {
                mma_f16(s_[0][nf], qa[0], kbf[nf]);
                mma_f16(s_[1][nf], qa[1], kbf[nf]);
            }
        }

        // ---- per-warp softmax (log2 domain, bare ex2) ----
        const bool needmask = (kb + 63 > qbase + wq);
        uint32_t P2[2][4][4];
#pragma unroll
        for (int mf = 0; mf < 2; mf++) {
            const int gr0 = qbase + wq + mf * 16 + lq;
            const int gr1 = gr0 + 8;
            float mx0 = -CUDART_INF_F, mx1 = -CUDART_INF_F;
#pragma unroll
            for (int nf = 0; nf < 8; nf++) {
                if (needmask) {
                    const int c0 = kb + nf * 8 + 2 * lr;
                    if (c0 > gr0)     s_[mf][nf][0] = -CUDART_INF_F;
                    if (c0 + 1 > gr0) s_[mf][nf][1] = -CUDART_INF_F;
                    if (c0 > gr1)     s_[mf][nf][2] = -CUDART_INF_F;
                    if (c0 + 1 > gr1) s_[mf][nf][3] = -CUDART_INF_F;
                }
                mx0 = fmaxf(mx0, fmaxf(s_[mf][nf][0], s_[mf][nf][1]));
                mx1 = fmaxf(mx1, fmaxf(s_[mf][nf][2], s_[mf][nf][3]));
            }
#pragma unroll
            for (int msk = 1; msk < 4; msk <<= 1) {
                mx0 = fmaxf(mx0, __shfl_xor_sync(0xffffffffu, mx0, msk));
                mx1 = fmaxf(mx1, __shfl_xor_sync(0xffffffffu, mx1, msk));
            }
            const float nm0 = fmaxf(mm[mf][0], mx0);
            const float nm1 = fmaxf(mm[mf][1], mx1);
            const float al0 = ex2f(mm[mf][0] - nm0);
            const float al1 = ex2f(mm[mf][1] - nm1);
            mm[mf][0] = nm0; mm[mf][1] = nm1;

            float sm0 = 0.f, sm1 = 0.f;
#pragma unroll
            for (int nf = 0; nf < 8; nf++) {
                float p0 = ex2f(s_[mf][nf][0] - nm0);
                float p1 = ex2f(s_[mf][nf][1] - nm0);
                float p2 = ex2f(s_[mf][nf][2] - nm1);
                float p3 = ex2f(s_[mf][nf][3] - nm1);
                sm0 += p0 + p1; sm1 += p2 + p3;
                s_[mf][nf][0] = p0; s_[mf][nf][1] = p1;
                s_[mf][nf][2] = p2; s_[mf][nf][3] = p3;
            }
#pragma unroll
            for (int msk = 1; msk < 4; msk <<= 1) {
                sm0 += __shfl_xor_sync(0xffffffffu, sm0, msk);
                sm1 += __shfl_xor_sync(0xffffffffu, sm1, msk);
            }
            ll[mf][0] = ll[mf][0] * al0 + sm0;
            ll[mf][1] = ll[mf][1] * al1 + sm1;
#pragma unroll
            for (int nf = 0; nf < 16; nf++) {
                o[mf][nf][0] *= al0; o[mf][nf][1] *= al0;
                o[mf][nf][2] *= al1; o[mf][nf][3] *= al1;
            }
#pragma unroll
            for (int kf = 0; kf < 4; kf++) {
                P2[mf][kf][0] = packh2(s_[mf][2 * kf][0],     s_[mf][2 * kf][1]);
                P2[mf][kf][1] = packh2(s_[mf][2 * kf][2],     s_[mf][2 * kf][3]);
                P2[mf][kf][2] = packh2(s_[mf][2 * kf + 1][0], s_[mf][2 * kf + 1][1]);
                P2[mf][kf][3] = packh2(s_[mf][2 * kf + 1][2], s_[mf][2 * kf + 1][3]);
            }
        }

        // ---- O += P @ V ----
#pragma unroll
        for (int kf = 0; kf < 4; kf++) {
            uint32_t vbf[16][2];
#pragma unroll
            for (int p = 0; p < 8; p++)
                LDSM_X4(vbf[2 * p][0], vbf[2 * p][1], vbf[2 * p + 1][0], vbf[2 * p + 1][1],
                        vsb + vb_lane + p * (16 * 272) + kf * 32);
#pragma unroll
            for (int nf = 0; nf < 16; nf++) {
                mma_f16(o[0][nf], P2[0][kf], vbf[nf]);
                mma_f16(o[1][nf], P2[1][kf], vbf[nf]);
            }
        }
    }

    // ---- merge key-halves: wc=1 publishes (fp32), wc=0 combines + stores ----
    float* Ox = (float*)smc;                 // [4][32][132] fp32
    float* St = Ox + 4 * 32 * 132;           // [128][2]
    __syncthreads();
    if (wc == 1) {
        float* ob = Ox + wr * 32 * 132;
#pragma unroll
        for (int mf = 0; mf < 2; mf++) {
            const int row0 = mf * 16 + lq;
#pragma unroll
            for (int nf = 0; nf < 16; nf++) {
                const int col = nf * 8 + 2 * lr;
                *(float2*)&ob[row0 * 132 + col]       = make_float2(o[mf][nf][0], o[mf][nf][1]);
                *(float2*)&ob[(row0 + 8) * 132 + col] = make_float2(o[mf][nf][2], o[mf][nf][3]);
            }
            if (lr == 0) {
                float* st = St + (wr * 32 + row0) * 2;
                st[0] = mm[mf][0]; st[1] = ll[mf][0];
                st[16] = mm[mf][1]; st[17] = ll[mf][1];
            }
        }
    }
    __syncthreads();
    if (wc == 0) {
        const float* ob = Ox + wr * 32 * 132;
#pragma unroll
        for (int mf = 0; mf < 2; mf++) {
            const int row0 = mf * 16 + lq;
            const float* st = St + (wr * 32 + row0) * 2;
            const float mo0 = st[0],  lo0 = st[1];
            const float mo1 = st[16], lo1 = st[17];
            const float M0 = fmaxf(mm[mf][0], mo0);
            const float M1 = fmaxf(mm[mf][1], mo1);
            const float as0 = ex2f(mm[mf][0] - M0), ao0 = ex2f(mo0 - M0);
            const float as1 = ex2f(mm[mf][1] - M1), ao1 = ex2f(mo1 - M1);
            const float inv0 = rcpf(ll[mf][0] * as0 + lo0 * ao0);
            const float inv1 = rcpf(ll[mf][1] * as1 + lo1 * ao1);
            const float fs0 = as0 * inv0, fo0 = ao0 * inv0;
            const float fs1 = as1 * inv1, fo1 = ao1 * inv1;
            const size_t r0 = rowbase + qbase + wq + row0;
            const size_t r1 = r0 + 8;
#pragma unroll
            for (int nf = 0; nf < 16; nf++) {
                const int col = nf * 8 + 2 * lr;
                float2 q0 = *(const float2*)&ob[row0 * 132 + col];
                float2 q1 = *(const float2*)&ob[(row0 + 8) * 132 + col];
                *(uint32_t*)(C + r0 * 2048 + qcol + col) =
                    packh2(o[mf][nf][0] * fs0 + q0.x * fo0,
                           o[mf][nf][1] * fs0 + q0.y * fo0);
                *(uint32_t*)(C + r1 * 2048 + qcol + col) =
                    packh2(o[mf][nf][2] * fs1 + q1.x * fo1,
                           o[mf][nf][3] * fs1 + q1.y * fo1);
            }
        }
    }
#undef KV_LOAD
}

// ---------------------------------------------------------------------------
extern "C" void kernel_launch(void* const* d_in, const int* in_sizes, int n_in,
                              void* d_out, int out_size)
{
    const float* x  = (const float*)d_in[0];
    const float* Wq = (const float*)d_in[1];
    const float* Wk = (const float*)d_in[2];
    const float* Wv = (const float*)d_in[3];
    const float* Wo = (const float*)d_in[4];
    const float* bo = (const float*)d_in[5];

    const int M = in_sizes[0] / D_IN;   // 4096
    const int B = M / SEQ;              // 2

    __half *Xh, *WqT, *WkT, *WvT, *WoT, *Qh, *Kh, *Vt, *Ch;
    cudaGetSymbolAddress((void**)&Xh,  g_Xh);
    cudaGetSymbolAddress((void**)&WqT, g_WqT);
    cudaGetSymbolAddress((void**)&WkT, g_WkT);
    cudaGetSymbolAddress((void**)&WvT, g_WvT);
    cudaGetSymbolAddress((void**)&WoT, g_WoT);
    cudaGetSymbolAddress((void**)&Qh,  g_Qh);
    cudaGetSymbolAddress((void**)&Kh,  g_Kh);
    cudaGetSymbolAddress((void**)&Vt,  g_Vt);
    cudaGetSymbolAddress((void**)&Ch,  g_Ch);

    cudaFuncSetAttribute(gemm_h<true>,
                         cudaFuncAttributeMaxDynamicSharedMemorySize, GEMM_SMEM);
    cudaFuncSetAttribute(gemm_h<false>,
                         cudaFuncAttributeMaxDynamicSharedMemorySize, GEMM_SMEM);
    cudaFuncSetAttribute(attn_h,
                         cudaFuncAttributeMaxDynamicSharedMemorySize, ATTN_SMEM);

    // prepass: fp16 conversions + paired weight transposes
    cvt_x<<<(M * D_IN) / 1024, 256>>>(x, Xh);
    transpose2_h<<<dim3(64, 64, 2), dim3(32, 8)>>>(Wq, WqT, Wo, WoT, 2048, 2048);
    transpose2_h<<<dim3(16, 64, 2), dim3(32, 8)>>>(Wk, WkT, Wv, WvT, 2048, 512);

    // fused QKV projection: N = 2048 (Q) + 512 (K) + 512 (V^T) = 3072
    gemm_h<true><<<dim3(24, M / 128), 256, GEMM_SMEM>>>(
        Xh, WqT, WkT, WvT, Qh, Kh, Vt, nullptr, nullptr);

    attn_h<<<dim3(SEQ / 128, B * 16), 256, ATTN_SMEM>>>(Qh, Kh, Vt, Ch);

    // output projection + bias (fp32 out)
    gemm_h<false><<<dim3(16, M / 128), 256, GEMM_SMEM>>>(
        Ch, WoT, nullptr, nullptr, nullptr, nullptr, nullptr, (float*)d_out, bo);
}